// round 13
// baseline (speedup 1.0000x reference)
#include <cuda_runtime.h>
#include <cuda_bf16.h>
#include <math.h>
#include <stdint.h>

#define BB  4
#define PP  2048
#define QQ  1024
#define QNN 32
#define DD  256
#define HH  128

// ---------------- persistent scratch ----------------
__device__ float g_pA[BB*PP*DD];
__device__ float g_pB[BB*PP*DD];
__device__ float g_qA[BB*QQ*DD];
__device__ float g_qB[BB*QQ*DD];
__device__ float g_quA[BB*QNN*DD];
__device__ float g_quB[BB*QNN*DD];
__device__ float g_selfp[BB*PP*DD];
__device__ float g_selfq[BB*QQ*DD];
__device__ float g_selfqu[BB*QNN*DD];
__device__ __nv_bfloat16 g_Yphi[BB*DD*PP];
__device__ __nv_bfloat16 g_Yplo[BB*DD*PP];
__device__ __nv_bfloat16 g_Yqhi[BB*DD*QQ];
__device__ __nv_bfloat16 g_Yqlo[BB*DD*QQ];
__device__ __nv_bfloat16 g_Gpbf[(size_t)BB*PP*PP];
__device__ __nv_bfloat16 g_Gqbf[(size_t)BB*QQ*QQ];
__device__ __nv_bfloat16 g_Aphi[BB*PP*DD];
__device__ __nv_bfloat16 g_Aplo[BB*PP*DD];
__device__ __nv_bfloat16 g_Aqhi[BB*QQ*DD];
__device__ __nv_bfloat16 g_Aqlo[BB*QQ*DD];
__device__ __nv_bfloat16 g_Aquhi[BB*QNN*DD];
__device__ __nv_bfloat16 g_Aqulo[BB*QNN*DD];
__device__ __nv_bfloat16 g_Wth[294912];
__device__ __nv_bfloat16 g_Wtl[294912];
#define OFF_SELF 0
#define OFF_PPW  65536
#define OFF_QQW  131072
#define OFF_PW   196608
#define OFF_QW   229376
#define OFF_QUW  262144
__device__ float g_rsp[BB*PP];
__device__ float g_rsq[BB*QQ];
__device__ float g_coefp[BB*PP];
__device__ float g_coefq[BB*QQ];
__device__ float g_coefqu[BB*QNN];
__device__ float g_sppart[BB*16*DD];
__device__ float g_sqpart[BB*8*DD];
__device__ float g_vqd[BB*DD];
__device__ float g_vqup[BB*DD];
__device__ float g_vquq[BB*DD];

// ---------------- asm helpers ----------------
#define CPA(dst, src) asm volatile("cp.async.cg.shared.global [%0], [%1], 16;" :: "r"(dst), "l"(src) : "memory")
#define CPC() asm volatile("cp.async.commit_group;" ::: "memory")
#define CPW1() asm volatile("cp.async.wait_group 1;" ::: "memory")
#define CPW0() asm volatile("cp.async.wait_group 0;" ::: "memory")
#define LDSM4(r0, r1, r2, r3, addr) \
    asm volatile("ldmatrix.sync.aligned.m8n8.x4.shared.b16 {%0,%1,%2,%3}, [%4];" \
        : "=r"(r0), "=r"(r1), "=r"(r2), "=r"(r3) : "r"(addr))

__device__ __forceinline__ void mma_bf16(float c[4], uint32_t a0, uint32_t a1,
                                         uint32_t a2, uint32_t a3,
                                         uint32_t b0, uint32_t b1) {
    asm volatile(
        "mma.sync.aligned.m16n8k16.row.col.f32.bf16.bf16.f32 "
        "{%0,%1,%2,%3}, {%4,%5,%6,%7}, {%8,%9}, {%0,%1,%2,%3};"
        : "+f"(c[0]), "+f"(c[1]), "+f"(c[2]), "+f"(c[3])
        : "r"(a0), "r"(a1), "r"(a2), "r"(a3), "r"(b0), "r"(b1));
}

__device__ __forceinline__ void split_pack2(float x, float y, uint32_t& h, uint32_t& l) {
    __nv_bfloat16 hx = __float2bfloat16(x), hy = __float2bfloat16(y);
    float rx = x - __bfloat162float(hx), ry = y - __bfloat162float(hy);
    __nv_bfloat16 lx = __float2bfloat16(rx), ly = __float2bfloat16(ry);
    h = (uint32_t)__bfloat16_as_ushort(hy) << 16 | __bfloat16_as_ushort(hx);
    l = (uint32_t)__bfloat16_as_ushort(ly) << 16 | __bfloat16_as_ushort(lx);
}

// ---------------- PREP über-kernel ----------------
__global__ __launch_bounds__(256)
void prep_kernel(const int* __restrict__ Gp, const int* __restrict__ Gq,
                 const int* __restrict__ pm, const int* __restrict__ qm,
                 const int* __restrict__ qum,
                 const float* __restrict__ W_self, const float* __restrict__ W_pp,
                 const float* __restrict__ W_qq, const float* __restrict__ W_p,
                 const float* __restrict__ W_q, const float* __restrict__ W_qu) {
    __shared__ float shp[2112];
    int bx = blockIdx.x, tid = threadIdx.x;
    if (bx < 1024) {
        int b = bx >> 8, xtile = bx & 255;
        for (int i = tid; i < PP; i += 256) shp[i] = (float)pm[b*PP + i];
        __syncthreads();
        int warp = tid >> 5, lane = tid & 31;
        int row = xtile * 8 + warp;
        const int* g = Gp + ((size_t)b*PP + row) * PP;
        __nv_bfloat16* go = g_Gpbf + ((size_t)b*PP + row) * PP;
        float s = 0.f;
        for (int j = lane * 4; j < PP; j += 128) {
            int4 v = *(const int4*)(g + j);
            uint32_t r0 = (v.x ? 0x3F80u : 0u) | ((v.y ? 0x3F80u : 0u) << 16);
            uint32_t r1 = (v.z ? 0x3F80u : 0u) | ((v.w ? 0x3F80u : 0u) << 16);
            *(uint2*)(go + j) = make_uint2(r0, r1);
            s += shp[j] * (float)v.x + shp[j+1] * (float)v.y
               + shp[j+2] * (float)v.z + shp[j+3] * (float)v.w;
        }
        #pragma unroll
        for (int o = 16; o; o >>= 1) s += __shfl_xor_sync(0xffffffffu, s, o);
        if (lane == 0)
            g_coefp[b*PP + row] = pm[b*PP + row] ? 1.f / fmaxf(s, 1.f) : 0.f;
    } else if (bx < 1536) {
        int i2 = bx - 1024;
        int b = i2 >> 7, xtile = i2 & 127;
        float ps = 0.f;
        for (int i = tid; i < PP; i += 256) ps += (float)pm[b*PP + i];
        for (int i = tid; i < QQ; i += 256) shp[i] = (float)qm[b*QQ + i];
        shp[1024 + tid] = ps;
        __syncthreads();
        if (tid < 128) shp[1024 + tid] += shp[1024 + tid + 128];
        __syncthreads();
        if (tid < 64) shp[1024 + tid] += shp[1024 + tid + 64];
        __syncthreads();
        if (tid < 32) {
            float v = shp[1024 + tid] + shp[1024 + tid + 32];
            #pragma unroll
            for (int o = 16; o; o >>= 1) v += __shfl_xor_sync(0xffffffffu, v, o);
            if (tid == 0) shp[2048] = v;
        }
        __syncthreads();
        float psum = shp[2048];
        int warp = tid >> 5, lane = tid & 31;
        int row = xtile * 8 + warp;
        const int* g = Gq + ((size_t)b*QQ + row) * QQ;
        __nv_bfloat16* go = g_Gqbf + ((size_t)b*QQ + row) * QQ;
        float s = 0.f;
        for (int j = lane * 4; j < QQ; j += 128) {
            int4 v = *(const int4*)(g + j);
            uint32_t r0 = (v.x ? 0x3F80u : 0u) | ((v.y ? 0x3F80u : 0u) << 16);
            uint32_t r1 = (v.z ? 0x3F80u : 0u) | ((v.w ? 0x3F80u : 0u) << 16);
            *(uint2*)(go + j) = make_uint2(r0, r1);
            s += shp[j] * (float)v.x + shp[j+1] * (float)v.y
               + shp[j+2] * (float)v.z + shp[j+3] * (float)v.w;
        }
        #pragma unroll
        for (int o = 16; o; o >>= 1) s += __shfl_xor_sync(0xffffffffu, s, o);
        if (lane == 0)
            g_coefq[b*QQ + row] = qm[b*QQ + row] ? 1.f / fmaxf(psum + s, 1.f) : 0.f;
    } else if (bx == 1536) {
        for (int b = 0; b < BB; b++) {
            float s = 0.f;
            for (int i = tid; i < PP; i += 256) s += (float)pm[b*PP + i];
            for (int i = tid; i < QQ; i += 256) s += (float)qm[b*QQ + i];
            shp[tid] = s;
            __syncthreads();
            for (int o = 128; o; o >>= 1) { if (tid < o) shp[tid] += shp[tid + o]; __syncthreads(); }
            if (tid == 0) shp[1024 + b] = shp[0];
            __syncthreads();
        }
        if (tid < BB*QNN) {
            int b = tid / QNN;
            g_coefqu[tid] = qum[tid] ? 1.f / fmaxf(shp[1024 + b], 1.f) : 0.f;
        }
    } else {
        int w = bx - 1537;
        int z = w / 64, ww = w % 64;
        const float* W; int N; int off;
        switch (z) {
            case 0: W = W_self; N = 256; off = OFF_SELF; break;
            case 1: W = W_pp;   N = 256; off = OFF_PPW;  break;
            case 2: W = W_qq;   N = 256; off = OFF_QQW;  break;
            case 3: W = W_p;    N = 128; off = OFF_PW;   break;
            case 4: W = W_q;    N = 128; off = OFF_QW;   break;
            default: W = W_qu;  N = 128; off = OFF_QUW;  break;
        }
        int nb = (ww & 7) * 32, kb = (ww >> 3) * 32;
        if (nb >= N) return;
        int tx = tid & 31, ty = tid >> 5;
        #pragma unroll
        for (int r = 0; r < 32; r += 8)
            shp[(ty + r) * 33 + tx] = W[(size_t)(kb + ty + r) * N + nb + tx];
        __syncthreads();
        __nv_bfloat16* Wth = g_Wth + off;
        __nv_bfloat16* Wtl = g_Wtl + off;
        #pragma unroll
        for (int r = 0; r < 32; r += 8) {
            int n = nb + ty + r, k = kb + tx;
            float v = shp[tx * 33 + ty + r];
            __nv_bfloat16 h = __float2bfloat16(v);
            Wth[(size_t)n * 256 + k] = h;
            Wtl[(size_t)n * 256 + k] = __float2bfloat16(v - __bfloat162float(h));
        }
    }
}

// ---------------- asplit body + standalone ----------------
__device__ __forceinline__ void asplit_body(int lb, const float* __restrict__ P,
                                            const float* __restrict__ Q,
                                            const float* __restrict__ QU) {
    const float* A; __nv_bfloat16 *Ahi, *Alo; int l2;
    if (lb < 2048) { A = P; Ahi = g_Aphi; Alo = g_Aplo; l2 = lb; }
    else if (lb < 3072) { A = Q; Ahi = g_Aqhi; Alo = g_Aqlo; l2 = lb - 2048; }
    else { A = QU; Ahi = g_Aquhi; Alo = g_Aqulo; l2 = lb - 3072; }
    size_t i4 = ((size_t)l2 * 256 + threadIdx.x) * 4;
    float4 v = *(const float4*)(A + i4);
    uint32_t h0, l0, h1, l1;
    split_pack2(v.x, v.y, h0, l0);
    split_pack2(v.z, v.w, h1, l1);
    *(uint2*)(Ahi + i4) = make_uint2(h0, h1);
    *(uint2*)(Alo + i4) = make_uint2(l0, l1);
}

__global__ void asplit_all_kernel(const float* __restrict__ P, const float* __restrict__ Q,
                                  const float* __restrict__ QU) {
    asplit_body(blockIdx.x, P, Q, QU);
}

// ---------------- step-pre über-kernel: pws + asplit ----------------
__global__ __launch_bounds__(256)
void steppre_kernel(const float* __restrict__ pcur, const float* __restrict__ qcur,
                    const float* __restrict__ qucur,
                    const int* __restrict__ pmask, const int* __restrict__ qmask,
                    const float* __restrict__ Wn, const float* __restrict__ bn) {
    int bx = blockIdx.x;
    if (bx >= 96) { asplit_body(bx - 96, pcur, qcur, qucur); return; }
    int b = bx / 24, chunk = bx % 24;
    int tid = threadIdx.x, wid = tid >> 5, lane = tid & 31;
    const float* node; const int* mask; float* rsout; float* sout; int rowbase;
    if (chunk < 16) {
        node = pcur + (size_t)b*PP*DD; mask = pmask + b*PP;
        rsout = g_rsp + b*PP; sout = g_sppart + (b*16 + chunk)*DD; rowbase = chunk * 128;
    } else {
        node = qcur + (size_t)b*QQ*DD; mask = qmask + b*QQ;
        rsout = g_rsq + b*QQ; sout = g_sqpart + (b*8 + (chunk - 16))*DD; rowbase = (chunk - 16) * 128;
    }
    __shared__ float wsh[DD];
    __shared__ float wrow[128];
    for (int k = tid; k < DD; k += 256) wsh[k] = Wn[k];
    __syncthreads();
    float bv = bn[0];
    #pragma unroll
    for (int r = 0; r < 16; r++) {
        int lrow = wid * 16 + r;
        const float* nrow = node + (size_t)(rowbase + lrow) * DD;
        float s = 0.f;
        #pragma unroll
        for (int k = lane; k < DD; k += 32) s += nrow[k] * wsh[k];
        #pragma unroll
        for (int o = 16; o; o >>= 1) s += __shfl_xor_sync(0xffffffffu, s, o);
        if (lane == 0) {
            float sig = 1.f / (1.f + expf(-(s + bv)));
            float w = mask[rowbase + lrow] ? sig : 0.f;
            wrow[lrow] = w;
            rsout[rowbase + lrow] = w;
        }
    }
    __syncthreads();
    float acc = 0.f;
    #pragma unroll 4
    for (int i = 0; i < 128; i++) {
        float w = wrow[i];
        if (w != 0.f) acc += w * node[(size_t)(rowbase + i) * DD + tid];
    }
    sout[tid] = acc;
}

// ---------------- shared GEMM mainloop (cp.async dbuf + ldmatrix, ILP-ordered) ----------------
#define KCP2 40
#define GST_B 40960
#define GEMM_SMEM (2*GST_B)

__device__ __forceinline__ void gemm_mainloop(
        const __nv_bfloat16* __restrict__ Ahi, const __nv_bfloat16* __restrict__ Alo,
        const __nv_bfloat16* __restrict__ Wth, const __nv_bfloat16* __restrict__ Wtl,
        int bm, int bn, float c[2][8][4], char* smem) {
    uint32_t sb = (uint32_t)__cvta_generic_to_shared(smem);

    int tid = threadIdx.x, wid = tid >> 5, lane = tid & 31;
    int wm = wid >> 1, wn = wid & 1;
    int m8 = lane >> 3, r8 = lane & 7;
    int rowoff = r8 + ((m8 & 1) ? 8 : 0);
    int koff8 = (m8 >= 2) ? 8 : 0;

    auto issue = [&](int ch, int st) {
        uint32_t base = sb + st * GST_B;
        int k0 = ch * 32;
        #pragma unroll
        for (int it = 0; it < 2; it++) {
            int u = tid + it * 256;
            int row = u >> 2, c8 = u & 3;
            size_t src = (size_t)(bm + row) * DD + k0 + c8 * 8;
            CPA(base + row * 80 + c8 * 16, Ahi + src);
            CPA(base + 10240 + row * 80 + c8 * 16, Alo + src);
        }
        #pragma unroll
        for (int it = 0; it < 2; it++) {
            int u = tid + it * 256;
            int n = u >> 2, c8 = u & 3;
            size_t src = (size_t)(bn + n) * 256 + k0 + c8 * 8;
            CPA(base + 20480 + n * 80 + c8 * 16, Wth + src);
            CPA(base + 30720 + n * 80 + c8 * 16, Wtl + src);
        }
    };

    issue(0, 0);
    CPC();
    int buf = 0;
    for (int ch = 0; ch < 8; ch++) {
        bool hn = (ch < 7);
        if (hn) { issue(ch + 1, buf ^ 1); CPC(); }
        if (hn) { CPW1(); } else { CPW0(); }
        __syncthreads();
        uint32_t base = sb + buf * GST_B;
        #pragma unroll
        for (int kt = 0; kt < 2; kt++) {
            int kcol = kt * 16 + koff8;
            uint32_t ah[2][4], al[2][4];
            #pragma unroll
            for (int mt = 0; mt < 2; mt++) {
                uint32_t aoff = (uint32_t)((wm*32 + mt*16 + rowoff) * KCP2 + kcol) * 2;
                LDSM4(ah[mt][0], ah[mt][1], ah[mt][2], ah[mt][3], base + aoff);
                LDSM4(al[mt][0], al[mt][1], al[mt][2], al[mt][3], base + 10240 + aoff);
            }
            #pragma unroll
            for (int j = 0; j < 4; j++) {
                uint32_t woff = (uint32_t)((wn*64 + j*16 + rowoff) * KCP2 + kcol) * 2;
                uint32_t wh0, wh1, wh2, wh3, wl0, wl1, wl2, wl3;
                LDSM4(wh0, wh1, wh2, wh3, base + 20480 + woff);
                LDSM4(wl0, wl1, wl2, wl3, base + 30720 + woff);
                mma_bf16(c[0][2*j],   ah[0][0], ah[0][1], ah[0][2], ah[0][3], wh0, wh2);
                mma_bf16(c[1][2*j],   ah[1][0], ah[1][1], ah[1][2], ah[1][3], wh0, wh2);
                mma_bf16(c[0][2*j+1], ah[0][0], ah[0][1], ah[0][2], ah[0][3], wh1, wh3);
                mma_bf16(c[1][2*j+1], ah[1][0], ah[1][1], ah[1][2], ah[1][3], wh1, wh3);
                mma_bf16(c[0][2*j],   al[0][0], al[0][1], al[0][2], al[0][3], wh0, wh2);
                mma_bf16(c[1][2*j],   al[1][0], al[1][1], al[1][2], al[1][3], wh0, wh2);
                mma_bf16(c[0][2*j+1], al[0][0], al[0][1], al[0][2], al[0][3], wh1, wh3);
                mma_bf16(c[1][2*j+1], al[1][0], al[1][1], al[1][2], al[1][3], wh1, wh3);
                mma_bf16(c[0][2*j],   ah[0][0], ah[0][1], ah[0][2], ah[0][3], wl0, wl2);
                mma_bf16(c[1][2*j],   ah[1][0], ah[1][1], ah[1][2], ah[1][3], wl0, wl2);
                mma_bf16(c[0][2*j+1], ah[0][0], ah[0][1], ah[0][2], ah[0][3], wl1, wl3);
                mma_bf16(c[1][2*j+1], ah[1][0], ah[1][1], ah[1][2], ah[1][3], wl1, wl3);
            }
        }
        __syncthreads();
        buf ^= 1;
    }
}

__device__ __forceinline__ void gemm_epi_self(float c[2][8][4], float* Cself,
                                              const float* bias, int bm, int bn, int N) {
    int tid = threadIdx.x, wid = tid >> 5, lane = tid & 31;
    int wm = wid >> 1, wn = wid & 1;
    #pragma unroll
    for (int mt = 0; mt < 2; mt++)
        #pragma unroll
        for (int h = 0; h < 2; h++) {
            int row = bm + wm * 32 + mt * 16 + (lane >> 2) + h * 8;
            float* orow = Cself + (size_t)row * N;
            #pragma unroll
            for (int nt = 0; nt < 8; nt++) {
                int col = bn + wn * 64 + nt * 8 + (lane & 3) * 2;
                float2 o;
                o.x = c[mt][nt][h * 2 + 0] + bias[col];
                o.y = c[mt][nt][h * 2 + 1] + bias[col + 1];
                *(float2*)(orow + col) = o;
            }
        }
}

// step-phase GEMM + vec über-kernel
__global__ __launch_bounds__(256)
void gemm_all_kernel(const float* __restrict__ b_self,
                     const float* __restrict__ Wqd, const float* __restrict__ Wqup,
                     const float* __restrict__ Wquq) {
    extern __shared__ char gsm[];
    int idx = blockIdx.x;
    if (idx >= 386) {
        int v = idx - 386;
        int b = v & 3, sel = v >> 2, tid = threadIdx.x;
        float* sh = (float*)gsm;
        const float* W = (sel == 0) ? Wqd : (sel == 1) ? Wqup : Wquq;
        float* out = (sel == 0) ? g_vqd : (sel == 1) ? g_vqup : g_vquq;
        float sv = 0.f;
        if (sel < 2) {
            #pragma unroll
            for (int cc = 0; cc < 16; cc++) sv += g_sppart[(b*16 + cc)*DD + tid];
        } else {
            #pragma unroll
            for (int cc = 0; cc < 8; cc++) sv += g_sqpart[(b*8 + cc)*DD + tid];
        }
        sh[tid] = sv;
        __syncthreads();
        float acc = 0.f;
        #pragma unroll 8
        for (int k = 0; k < DD; k++) acc += sh[k] * W[(size_t)k*DD + tid];
        out[b*DD + tid] = acc;
        return;
    }
    const __nv_bfloat16 *Ahi, *Alo, *WthS, *WtlS, *WthY, *WtlY;
    float* Cself; const float* rowscale;
    __nv_bfloat16 *Yhi, *Ylo; int NNbatch, bm, by;
    if (idx < 256) {
        by = idx >> 6; bm = (idx & 63) * 128;
        Ahi = g_Aphi; Alo = g_Aplo;
        WthY = g_Wth + OFF_PPW; WtlY = g_Wtl + OFF_PPW;
        Cself = g_selfp; rowscale = g_rsp; Yhi = g_Yphi; Ylo = g_Yplo; NNbatch = PP;
    } else if (idx < 384) {
        int i2 = idx - 256;
        by = i2 >> 5; bm = (i2 & 31) * 128;
        Ahi = g_Aqhi; Alo = g_Aqlo;
        WthY = g_Wth + OFF_QQW; WtlY = g_Wtl + OFF_QQW;
        Cself = g_selfq; rowscale = g_rsq; Yhi = g_Yqhi; Ylo = g_Yqlo; NNbatch = QQ;
    } else {
        by = idx - 384; bm = 0;
        Ahi = g_Aquhi; Alo = g_Aqulo;
        WthY = nullptr; WtlY = nullptr;
        Cself = g_selfqu; rowscale = nullptr; Yhi = nullptr; Ylo = nullptr; NNbatch = 0;
    }
    WthS = g_Wth + OFF_SELF; WtlS = g_Wtl + OFF_SELF;
    int mode = by >> 1;
    int bn = (by & 1) * 128;
    const __nv_bfloat16* Wth = mode ? WthY : WthS;
    const __nv_bfloat16* Wtl = mode ? WtlY : WtlS;

    float c[2][8][4];
    #pragma unroll
    for (int mt = 0; mt < 2; mt++)
        #pragma unroll
        for (int nt = 0; nt < 8; nt++)
            #pragma unroll
            for (int r = 0; r < 4; r++) c[mt][nt][r] = 0.f;

    gemm_mainloop(Ahi, Alo, Wth, Wtl, bm, bn, c, gsm);

    int tid = threadIdx.x, wid = tid >> 5, lane = tid & 31;
    int wm = wid >> 1, wn = wid & 1;
    if (mode == 0) {
        gemm_epi_self(c, Cself, b_self, bm, bn, DD);
    } else {
        #pragma unroll
        for (int mt = 0; mt < 2; mt++)
            #pragma unroll
            for (int h = 0; h < 2; h++) {
                int gr = bm + wm * 32 + mt * 16 + (lane >> 2) + h * 8;
                float rs = rowscale[gr];
                int b = gr / NNbatch;
                int i = gr - b * NNbatch;
                #pragma unroll
                for (int nt = 0; nt < 8; nt++) {
                    int col = bn + wn * 64 + nt * 8 + (lane & 3) * 2;
                    size_t base = ((size_t)b * DD + col) * NNbatch + i;
                    float v0 = c[mt][nt][h * 2 + 0] * rs;
                    float v1 = c[mt][nt][h * 2 + 1] * rs;
                    __nv_bfloat16 h0 = __float2bfloat16(v0);
                    __nv_bfloat16 h1 = __float2bfloat16(v1);
                    Yhi[base] = h0;
                    Yhi[base + NNbatch] = h1;
                    Ylo[base] = __float2bfloat16(v0 - __bfloat162float(h0));
                    Ylo[base + NNbatch] = __float2bfloat16(v1 - __bfloat162float(h1));
                }
            }
    }
}

// merged output projections: [0,64) p, [64,96) q, 96 qu
__global__ __launch_bounds__(256)
void gemm_out_kernel(const float* __restrict__ b_p, const float* __restrict__ b_q,
                     const float* __restrict__ b_qu, float* __restrict__ out) {
    extern __shared__ char gsm[];
    int bx = blockIdx.x;
    const __nv_bfloat16 *Ahi, *Alo, *Wth, *Wtl; const float* bias; float* O; int bm;
    if (bx < 64) {
        Ahi = g_Aphi; Alo = g_Aplo; Wth = g_Wth + OFF_PW; Wtl = g_Wtl + OFF_PW;
        bias = b_p; O = out; bm = bx * 128;
    } else if (bx < 96) {
        Ahi = g_Aqhi; Alo = g_Aqlo; Wth = g_Wth + OFF_QW; Wtl = g_Wtl + OFF_QW;
        bias = b_q; O = out + (size_t)BB*PP*HH; bm = (bx - 64) * 128;
    } else {
        Ahi = g_Aquhi; Alo = g_Aqulo; Wth = g_Wth + OFF_QUW; Wtl = g_Wtl + OFF_QUW;
        bias = b_qu; O = out + (size_t)BB*PP*HH + (size_t)BB*QQ*HH; bm = 0;
    }
    float c[2][8][4];
    #pragma unroll
    for (int mt = 0; mt < 2; mt++)
        #pragma unroll
        for (int nt = 0; nt < 8; nt++)
            #pragma unroll
            for (int r = 0; r < 4; r++) c[mt][nt][r] = 0.f;

    gemm_mainloop(Ahi, Alo, Wth, Wtl, bm, 0, c, gsm);
    gemm_epi_self(c, O, bias, bm, 0, HH);
}

// ---------------- adjacency: 3-stage pipeline, 3 CTAs/SM + qu_update ----------------
#define KC 32
#define KCP 40
#define AS_B 5120
#define BH_B 10240
#define ST_B (AS_B + 2*BH_B)       // 25600 per stage
#define ADJ_SMEM (3*ST_B)          // 76800 -> 3 CTAs/SM

__global__ __launch_bounds__(256, 3)
void adjq_kernel(const float* __restrict__ selfp, const float* __restrict__ selfq,
                 float* __restrict__ Op, float* __restrict__ Oq,
                 float* __restrict__ qunxt) {
    extern __shared__ __align__(16) char dsm[];
    int bx = blockIdx.x;
    int tid = threadIdx.x;
    if (bx >= 384) {
        int r = bx - 384;
        int b = r / QNN;
        float v = g_selfqu[(size_t)r*DD + tid] + g_coefqu[r] * (g_vqup[b*DD + tid] + g_vquq[b*DD + tid]);
        qunxt[(size_t)r*DD + tid] = fmaxf(v, 0.f);
        return;
    }
    uint32_t smemBase = (uint32_t)__cvta_generic_to_shared(dsm);

    const __nv_bfloat16 *Gbf, *Yh, *Yl; const float *S, *coef, *ev;
    float* O; int NN, b, mtile, nhalf;
    if (bx < 256) {
        nhalf = bx & 1;
        int rest = bx >> 1;
        b = rest >> 5; mtile = rest & 31; NN = PP;
        Gbf = g_Gpbf + (size_t)b*PP*PP;
        Yh = g_Yphi + (size_t)b*DD*PP;  Yl = g_Yplo + (size_t)b*DD*PP;
        S = selfp + (size_t)b*PP*DD;    coef = g_coefp + b*PP;
        ev = nullptr;                   O = Op + (size_t)b*PP*DD;
    } else {
        int i2 = bx - 256;
        nhalf = i2 & 1;
        int rest = i2 >> 1;
        b = rest >> 4; mtile = rest & 15; NN = QQ;
        Gbf = g_Gqbf + (size_t)b*QQ*QQ;
        Yh = g_Yqhi + (size_t)b*DD*QQ;  Yl = g_Yqlo + (size_t)b*DD*QQ;
        S = selfq + (size_t)b*QQ*DD;    coef = g_coefq + b*QQ;
        ev = g_vqd + b*DD;              O = Oq + (size_t)b*QQ*DD;
    }
    int bm = mtile * 64, bn = nhalf * 128;
    int wid = tid >> 5, lane = tid & 31;
    int wm = wid >> 2, wn = wid & 3;
    int m8 = lane >> 3, r8 = lane & 7;
    int rowoff = r8 + ((m8 & 1) ? 8 : 0);
    int koff8 = (m8 >= 2) ? 8 : 0;

    float c[2][4][4];
    #pragma unroll
    for (int mt = 0; mt < 2; mt++)
        #pragma unroll
        for (int nt = 0; nt < 4; nt++)
            #pragma unroll
            for (int r = 0; r < 4; r++) c[mt][nt][r] = 0.f;

    int arow = tid >> 2, ac8 = tid & 3;

    auto issue = [&](int k0, int stage) {
        uint32_t asb = smemBase + stage * ST_B;
        CPA(asb + arow * 80 + ac8 * 16, Gbf + (size_t)(bm + arow) * NN + k0 + ac8 * 8);
        uint32_t bhb = asb + AS_B;
        uint32_t blb = bhb + BH_B;
        #pragma unroll
        for (int it = 0; it < 2; it++) {
            int idx = tid + it * 256;
            int d = idx >> 2, c8 = idx & 3;
            size_t src = (size_t)(bn + d) * NN + k0 + c8 * 8;
            CPA(bhb + d * 80 + c8 * 16, Yh + src);
            CPA(blb + d * 80 + c8 * 16, Yl + src);
        }
    };

    const int nchunks = NN / KC;
    // prologue: fill stages 0,1 (prefetch distance 2)
    issue(0, 0); CPC();
    issue(KC, 1); CPC();

    int st = 0;
    for (int ch = 0; ch < nchunks; ch++) {
        int rem = nchunks - 1 - ch;
        if (rem >= 1) { CPW1(); } else { CPW0(); }
        __syncthreads();   // data for ch ready; stage (ch-1)%3 consumed by all warps
        int nx = ch + 2;
        if (nx < nchunks) {
            int nst = st + 2; if (nst >= 3) nst -= 3;
            issue(nx * KC, nst); CPC();
        }

        uint32_t stB = smemBase + st * ST_B;
        uint32_t asB = stB;
        uint32_t bhB = stB + AS_B;
        uint32_t blB = bhB + BH_B;

        #pragma unroll
        for (int kt = 0; kt < 2; kt++) {
            int kcol = kt * 16 + koff8;
            uint32_t a[2][4];
            #pragma unroll
            for (int mt = 0; mt < 2; mt++) {
                uint32_t aoff = (uint32_t)((wm*32 + mt*16 + rowoff) * KCP + kcol) * 2;
                LDSM4(a[mt][0], a[mt][1], a[mt][2], a[mt][3], asB + aoff);
            }
            uint32_t bh[2][4], bl[2][4];
            #pragma unroll
            for (int j = 0; j < 2; j++) {
                uint32_t boff = (uint32_t)((wn*32 + j*16 + rowoff) * KCP + kcol) * 2;
                LDSM4(bh[j][0], bh[j][1], bh[j][2], bh[j][3], bhB + boff);
                LDSM4(bl[j][0], bl[j][1], bl[j][2], bl[j][3], blB + boff);
            }
            mma_bf16(c[0][0], a[0][0], a[0][1], a[0][2], a[0][3], bh[0][0], bh[0][2]);
            mma_bf16(c[1][0], a[1][0], a[1][1], a[1][2], a[1][3], bh[0][0], bh[0][2]);
            mma_bf16(c[0][1], a[0][0], a[0][1], a[0][2], a[0][3], bh[0][1], bh[0][3]);
            mma_bf16(c[1][1], a[1][0], a[1][1], a[1][2], a[1][3], bh[0][1], bh[0][3]);
            mma_bf16(c[0][2], a[0][0], a[0][1], a[0][2], a[0][3], bh[1][0], bh[1][2]);
            mma_bf16(c[1][2], a[1][0], a[1][1], a[1][2], a[1][3], bh[1][0], bh[1][2]);
            mma_bf16(c[0][3], a[0][0], a[0][1], a[0][2], a[0][3], bh[1][1], bh[1][3]);
            mma_bf16(c[1][3], a[1][0], a[1][1], a[1][2], a[1][3], bh[1][1], bh[1][3]);
            mma_bf16(c[0][0], a[0][0], a[0][1], a[0][2], a[0][3], bl[0][0], bl[0][2]);
            mma_bf16(c[1][0], a[1][0], a[1][1], a[1][2], a[1][3], bl[0][0], bl[0][2]);
            mma_bf16(c[0][1], a[0][0], a[0][1], a[0][2], a[0][3], bl[0][1], bl[0][3]);
            mma_bf16(c[1][1], a[1][0], a[1][1], a[1][2], a[1][3], bl[0][1], bl[0][3]);
            mma_bf16(c[0][2], a[0][0], a[0][1], a[0][2], a[0][3], bl[1][0], bl[1][2]);
            mma_bf16(c[1][2], a[1][0], a[1][1], a[1][2], a[1][3], bl[1][0], bl[1][2]);
            mma_bf16(c[0][3], a[0][0], a[0][1], a[0][2], a[0][3], bl[1][1], bl[1][3]);
            mma_bf16(c[1][3], a[1][0], a[1][1], a[1][2], a[1][3], bl[1][1], bl[1][3]);
        }
        st++; if (st >= 3) st = 0;
    }

    #pragma unroll
    for (int mt = 0; mt < 2; mt++) {
        #pragma unroll
        for (int h = 0; h < 2; h++) {
            int row = bm + wm * 32 + mt * 16 + (lane >> 2) + h * 8;
            float cf = coef[row];
            const float* srow = S + (size_t)row * DD;
            float* orow = O + (size_t)row * DD;
            #pragma unroll
            for (int nt = 0; nt < 4; nt++) {
                int col = bn + wn * 32 + (nt >> 1) * 16 + (nt & 1) * 8 + (lane & 3) * 2;
                float v0 = c[mt][nt][h * 2 + 0];
                float v1 = c[mt][nt][h * 2 + 1];
                if (ev) { v0 += ev[col]; v1 += ev[col + 1]; }
                float2 s2 = *(const float2*)(srow + col);
                float2 o;
                o.x = fmaxf(s2.x + cf * v0, 0.f);
                o.y = fmaxf(s2.y + cf * v1, 0.f);
                *(float2*)(orow + col) = o;
            }
        }
    }
}

// ---------------- launch ----------------
extern "C" void kernel_launch(void* const* d_in, const int* in_sizes, int n_in,
                              void* d_out, int out_size) {
    const float* p_in   = (const float*)d_in[0];
    const float* q_in   = (const float*)d_in[1];
    const float* qu_in  = (const float*)d_in[2];
    const int*   pmask  = (const int*)d_in[3];
    const int*   qmask  = (const int*)d_in[4];
    const int*   qumask = (const int*)d_in[5];
    const int*   ppg    = (const int*)d_in[6];
    const int*   qqg    = (const int*)d_in[7];
    const float* W_node = (const float*)d_in[10];
    const float* b_node = (const float*)d_in[11];
    const float* W_self = (const float*)d_in[12];
    const float* b_self = (const float*)d_in[13];
    const float* W_pp   = (const float*)d_in[14];
    const float* W_qd   = (const float*)d_in[15];
    const float* W_qq   = (const float*)d_in[16];
    const float* W_qup  = (const float*)d_in[17];
    const float* W_quq  = (const float*)d_in[18];
    const float* W_p    = (const float*)d_in[19];
    const float* b_p    = (const float*)d_in[20];
    const float* W_q    = (const float*)d_in[21];
    const float* b_q    = (const float*)d_in[22];
    const float* W_qu   = (const float*)d_in[23];
    const float* b_qu   = (const float*)d_in[24];
    float* out = (float*)d_out;

    float *pA, *pB, *qA, *qB, *quA, *quB, *selfp, *selfq;
    cudaGetSymbolAddress((void**)&pA, g_pA);
    cudaGetSymbolAddress((void**)&pB, g_pB);
    cudaGetSymbolAddress((void**)&qA, g_qA);
    cudaGetSymbolAddress((void**)&qB, g_qB);
    cudaGetSymbolAddress((void**)&quA, g_quA);
    cudaGetSymbolAddress((void**)&quB, g_quB);
    cudaGetSymbolAddress((void**)&selfp, g_selfp);
    cudaGetSymbolAddress((void**)&selfq, g_selfq);

    cudaFuncSetAttribute(adjq_kernel, cudaFuncAttributeMaxDynamicSharedMemorySize, ADJ_SMEM);
    cudaFuncSetAttribute(gemm_all_kernel, cudaFuncAttributeMaxDynamicSharedMemorySize, GEMM_SMEM);
    cudaFuncSetAttribute(gemm_out_kernel, cudaFuncAttributeMaxDynamicSharedMemorySize, GEMM_SMEM);

    prep_kernel<<<1921, 256>>>(ppg, qqg, pmask, qmask, qumask,
                               W_self, W_pp, W_qq, W_p, W_q, W_qu);

    const float* pc = p_in;  const float* qc = q_in;  const float* quc = qu_in;
    float* pn = pA;  float* qn = qA;  float* qun = quA;

    for (int step = 0; step < 2; step++) {
        steppre_kernel<<<3200, 256>>>(pc, qc, quc, pmask, qmask, W_node, b_node);
        gemm_all_kernel<<<398, 256, GEMM_SMEM>>>(b_self, W_qd, W_qup, W_quq);
        adjq_kernel<<<512, 256, ADJ_SMEM>>>(selfp, selfq, pn, qn, qun);
        pc = pn; qc = qn; quc = qun;
        pn = pB; qn = qB; qun = quB;
    }

    asplit_all_kernel<<<3104, 256>>>(pc, qc, quc);
    gemm_out_kernel<<<97, 256, GEMM_SMEM>>>(b_p, b_q, b_qu, out);
}

// round 15
// speedup vs baseline: 1.3851x; 1.3851x over previous
#include <cuda_runtime.h>
#include <cuda_bf16.h>
#include <cuda_fp16.h>
#include <math.h>
#include <stdint.h>

#define BB  4
#define PP  2048
#define QQ  1024
#define QNN 32
#define DD  256
#define HH  128

// ---------------- persistent scratch ----------------
__device__ float g_pA[BB*PP*DD];
__device__ float g_pB[BB*PP*DD];
__device__ float g_qA[BB*QQ*DD];
__device__ float g_qB[BB*QQ*DD];
__device__ float g_quA[BB*QNN*DD];
__device__ float g_quB[BB*QNN*DD];
__device__ float g_selfp[BB*PP*DD];
__device__ float g_selfq[BB*QQ*DD];
__device__ float g_selfqu[BB*QNN*DD];
__device__ __half g_Ypf16[BB*DD*PP];
__device__ __half g_Yqf16[BB*DD*QQ];
__device__ __half g_Gpf16[(size_t)BB*PP*PP];
__device__ __half g_Gqf16[(size_t)BB*QQ*QQ];
__device__ __nv_bfloat16 g_Aphi[BB*PP*DD];
__device__ __nv_bfloat16 g_Aplo[BB*PP*DD];
__device__ __nv_bfloat16 g_Aqhi[BB*QQ*DD];
__device__ __nv_bfloat16 g_Aqlo[BB*QQ*DD];
__device__ __nv_bfloat16 g_Aquhi[BB*QNN*DD];
__device__ __nv_bfloat16 g_Aqulo[BB*QNN*DD];
__device__ __nv_bfloat16 g_Wth[294912];
__device__ __nv_bfloat16 g_Wtl[294912];
#define OFF_SELF 0
#define OFF_PPW  65536
#define OFF_QQW  131072
#define OFF_PW   196608
#define OFF_QW   229376
#define OFF_QUW  262144
__device__ float g_rsp[BB*PP];
__device__ float g_rsq[BB*QQ];
__device__ float g_coefp[BB*PP];
__device__ float g_coefq[BB*QQ];
__device__ float g_coefqu[BB*QNN];
__device__ float g_sppart[BB*16*DD];
__device__ float g_sqpart[BB*8*DD];
__device__ float g_vqd[BB*DD];
__device__ float g_vqup[BB*DD];
__device__ float g_vquq[BB*DD];

// ---------------- asm helpers ----------------
#define CPA(dst, src) asm volatile("cp.async.cg.shared.global [%0], [%1], 16;" :: "r"(dst), "l"(src) : "memory")
#define CPC() asm volatile("cp.async.commit_group;" ::: "memory")
#define CPW2() asm volatile("cp.async.wait_group 2;" ::: "memory")
#define CPW1() asm volatile("cp.async.wait_group 1;" ::: "memory")
#define CPW0() asm volatile("cp.async.wait_group 0;" ::: "memory")
#define LDSM4(r0, r1, r2, r3, addr) \
    asm volatile("ldmatrix.sync.aligned.m8n8.x4.shared.b16 {%0,%1,%2,%3}, [%4];" \
        : "=r"(r0), "=r"(r1), "=r"(r2), "=r"(r3) : "r"(addr))

__device__ __forceinline__ void mma_bf16(float c[4], uint32_t a0, uint32_t a1,
                                         uint32_t a2, uint32_t a3,
                                         uint32_t b0, uint32_t b1) {
    asm volatile(
        "mma.sync.aligned.m16n8k16.row.col.f32.bf16.bf16.f32 "
        "{%0,%1,%2,%3}, {%4,%5,%6,%7}, {%8,%9}, {%0,%1,%2,%3};"
        : "+f"(c[0]), "+f"(c[1]), "+f"(c[2]), "+f"(c[3])
        : "r"(a0), "r"(a1), "r"(a2), "r"(a3), "r"(b0), "r"(b1));
}

__device__ __forceinline__ void mma_f16(float c[4], uint32_t a0, uint32_t a1,
                                        uint32_t a2, uint32_t a3,
                                        uint32_t b0, uint32_t b1) {
    asm volatile(
        "mma.sync.aligned.m16n8k16.row.col.f32.f16.f16.f32 "
        "{%0,%1,%2,%3}, {%4,%5,%6,%7}, {%8,%9}, {%0,%1,%2,%3};"
        : "+f"(c[0]), "+f"(c[1]), "+f"(c[2]), "+f"(c[3])
        : "r"(a0), "r"(a1), "r"(a2), "r"(a3), "r"(b0), "r"(b1));
}

__device__ __forceinline__ void split_pack2(float x, float y, uint32_t& h, uint32_t& l) {
    __nv_bfloat16 hx = __float2bfloat16(x), hy = __float2bfloat16(y);
    float rx = x - __bfloat162float(hx), ry = y - __bfloat162float(hy);
    __nv_bfloat16 lx = __float2bfloat16(rx), ly = __float2bfloat16(ry);
    h = (uint32_t)__bfloat16_as_ushort(hy) << 16 | __bfloat16_as_ushort(hx);
    l = (uint32_t)__bfloat16_as_ushort(ly) << 16 | __bfloat16_as_ushort(lx);
}

// ---------------- PREP über-kernel (G -> fp16 now) ----------------
__global__ __launch_bounds__(256)
void prep_kernel(const int* __restrict__ Gp, const int* __restrict__ Gq,
                 const int* __restrict__ pm, const int* __restrict__ qm,
                 const int* __restrict__ qum,
                 const float* __restrict__ W_self, const float* __restrict__ W_pp,
                 const float* __restrict__ W_qq, const float* __restrict__ W_p,
                 const float* __restrict__ W_q, const float* __restrict__ W_qu) {
    __shared__ float shp[2112];
    int bx = blockIdx.x, tid = threadIdx.x;
    if (bx < 1024) {
        int b = bx >> 8, xtile = bx & 255;
        for (int i = tid; i < PP; i += 256) shp[i] = (float)pm[b*PP + i];
        __syncthreads();
        int warp = tid >> 5, lane = tid & 31;
        int row = xtile * 8 + warp;
        const int* g = Gp + ((size_t)b*PP + row) * PP;
        __half* go = g_Gpf16 + ((size_t)b*PP + row) * PP;
        float s = 0.f;
        for (int j = lane * 4; j < PP; j += 128) {
            int4 v = *(const int4*)(g + j);
            uint32_t r0 = (v.x ? 0x3C00u : 0u) | ((v.y ? 0x3C00u : 0u) << 16);
            uint32_t r1 = (v.z ? 0x3C00u : 0u) | ((v.w ? 0x3C00u : 0u) << 16);
            *(uint2*)(go + j) = make_uint2(r0, r1);
            s += shp[j] * (float)v.x + shp[j+1] * (float)v.y
               + shp[j+2] * (float)v.z + shp[j+3] * (float)v.w;
        }
        #pragma unroll
        for (int o = 16; o; o >>= 1) s += __shfl_xor_sync(0xffffffffu, s, o);
        if (lane == 0)
            g_coefp[b*PP + row] = pm[b*PP + row] ? 1.f / fmaxf(s, 1.f) : 0.f;
    } else if (bx < 1536) {
        int i2 = bx - 1024;
        int b = i2 >> 7, xtile = i2 & 127;
        float ps = 0.f;
        for (int i = tid; i < PP; i += 256) ps += (float)pm[b*PP + i];
        for (int i = tid; i < QQ; i += 256) shp[i] = (float)qm[b*QQ + i];
        shp[1024 + tid] = ps;
        __syncthreads();
        if (tid < 128) shp[1024 + tid] += shp[1024 + tid + 128];
        __syncthreads();
        if (tid < 64) shp[1024 + tid] += shp[1024 + tid + 64];
        __syncthreads();
        if (tid < 32) {
            float v = shp[1024 + tid] + shp[1024 + tid + 32];
            #pragma unroll
            for (int o = 16; o; o >>= 1) v += __shfl_xor_sync(0xffffffffu, v, o);
            if (tid == 0) shp[2048] = v;
        }
        __syncthreads();
        float psum = shp[2048];
        int warp = tid >> 5, lane = tid & 31;
        int row = xtile * 8 + warp;
        const int* g = Gq + ((size_t)b*QQ + row) * QQ;
        __half* go = g_Gqf16 + ((size_t)b*QQ + row) * QQ;
        float s = 0.f;
        for (int j = lane * 4; j < QQ; j += 128) {
            int4 v = *(const int4*)(g + j);
            uint32_t r0 = (v.x ? 0x3C00u : 0u) | ((v.y ? 0x3C00u : 0u) << 16);
            uint32_t r1 = (v.z ? 0x3C00u : 0u) | ((v.w ? 0x3C00u : 0u) << 16);
            *(uint2*)(go + j) = make_uint2(r0, r1);
            s += shp[j] * (float)v.x + shp[j+1] * (float)v.y
               + shp[j+2] * (float)v.z + shp[j+3] * (float)v.w;
        }
        #pragma unroll
        for (int o = 16; o; o >>= 1) s += __shfl_xor_sync(0xffffffffu, s, o);
        if (lane == 0)
            g_coefq[b*QQ + row] = qm[b*QQ + row] ? 1.f / fmaxf(psum + s, 1.f) : 0.f;
    } else if (bx == 1536) {
        for (int b = 0; b < BB; b++) {
            float s = 0.f;
            for (int i = tid; i < PP; i += 256) s += (float)pm[b*PP + i];
            for (int i = tid; i < QQ; i += 256) s += (float)qm[b*QQ + i];
            shp[tid] = s;
            __syncthreads();
            for (int o = 128; o; o >>= 1) { if (tid < o) shp[tid] += shp[tid + o]; __syncthreads(); }
            if (tid == 0) shp[1024 + b] = shp[0];
            __syncthreads();
        }
        if (tid < BB*QNN) {
            int b = tid / QNN;
            g_coefqu[tid] = qum[tid] ? 1.f / fmaxf(shp[1024 + b], 1.f) : 0.f;
        }
    } else {
        int w = bx - 1537;
        int z = w / 64, ww = w % 64;
        const float* W; int N; int off;
        switch (z) {
            case 0: W = W_self; N = 256; off = OFF_SELF; break;
            case 1: W = W_pp;   N = 256; off = OFF_PPW;  break;
            case 2: W = W_qq;   N = 256; off = OFF_QQW;  break;
            case 3: W = W_p;    N = 128; off = OFF_PW;   break;
            case 4: W = W_q;    N = 128; off = OFF_QW;   break;
            default: W = W_qu;  N = 128; off = OFF_QUW;  break;
        }
        int nb = (ww & 7) * 32, kb = (ww >> 3) * 32;
        if (nb >= N) return;
        int tx = tid & 31, ty = tid >> 5;
        #pragma unroll
        for (int r = 0; r < 32; r += 8)
            shp[(ty + r) * 33 + tx] = W[(size_t)(kb + ty + r) * N + nb + tx];
        __syncthreads();
        __nv_bfloat16* Wth = g_Wth + off;
        __nv_bfloat16* Wtl = g_Wtl + off;
        #pragma unroll
        for (int r = 0; r < 32; r += 8) {
            int n = nb + ty + r, k = kb + tx;
            float v = shp[tx * 33 + ty + r];
            __nv_bfloat16 h = __float2bfloat16(v);
            Wth[(size_t)n * 256 + k] = h;
            Wtl[(size_t)n * 256 + k] = __float2bfloat16(v - __bfloat162float(h));
        }
    }
}

// ---------------- asplit body + standalone ----------------
__device__ __forceinline__ void asplit_body(int lb, const float* __restrict__ P,
                                            const float* __restrict__ Q,
                                            const float* __restrict__ QU) {
    const float* A; __nv_bfloat16 *Ahi, *Alo; int l2;
    if (lb < 2048) { A = P; Ahi = g_Aphi; Alo = g_Aplo; l2 = lb; }
    else if (lb < 3072) { A = Q; Ahi = g_Aqhi; Alo = g_Aqlo; l2 = lb - 2048; }
    else { A = QU; Ahi = g_Aquhi; Alo = g_Aqulo; l2 = lb - 3072; }
    size_t i4 = ((size_t)l2 * 256 + threadIdx.x) * 4;
    float4 v = *(const float4*)(A + i4);
    uint32_t h0, l0, h1, l1;
    split_pack2(v.x, v.y, h0, l0);
    split_pack2(v.z, v.w, h1, l1);
    *(uint2*)(Ahi + i4) = make_uint2(h0, h1);
    *(uint2*)(Alo + i4) = make_uint2(l0, l1);
}

__global__ void asplit_all_kernel(const float* __restrict__ P, const float* __restrict__ Q,
                                  const float* __restrict__ QU) {
    asplit_body(blockIdx.x, P, Q, QU);
}

// ---------------- step-pre über-kernel: pws + asplit ----------------
__global__ __launch_bounds__(256)
void steppre_kernel(const float* __restrict__ pcur, const float* __restrict__ qcur,
                    const float* __restrict__ qucur,
                    const int* __restrict__ pmask, const int* __restrict__ qmask,
                    const float* __restrict__ Wn, const float* __restrict__ bn) {
    int bx = blockIdx.x;
    if (bx >= 96) { asplit_body(bx - 96, pcur, qcur, qucur); return; }
    int b = bx / 24, chunk = bx % 24;
    int tid = threadIdx.x, wid = tid >> 5, lane = tid & 31;
    const float* node; const int* mask; float* rsout; float* sout; int rowbase;
    if (chunk < 16) {
        node = pcur + (size_t)b*PP*DD; mask = pmask + b*PP;
        rsout = g_rsp + b*PP; sout = g_sppart + (b*16 + chunk)*DD; rowbase = chunk * 128;
    } else {
        node = qcur + (size_t)b*QQ*DD; mask = qmask + b*QQ;
        rsout = g_rsq + b*QQ; sout = g_sqpart + (b*8 + (chunk - 16))*DD; rowbase = (chunk - 16) * 128;
    }
    __shared__ float wsh[DD];
    __shared__ float wrow[128];
    for (int k = tid; k < DD; k += 256) wsh[k] = Wn[k];
    __syncthreads();
    float bv = bn[0];
    #pragma unroll
    for (int r = 0; r < 16; r++) {
        int lrow = wid * 16 + r;
        const float* nrow = node + (size_t)(rowbase + lrow) * DD;
        float s = 0.f;
        #pragma unroll
        for (int k = lane; k < DD; k += 32) s += nrow[k] * wsh[k];
        #pragma unroll
        for (int o = 16; o; o >>= 1) s += __shfl_xor_sync(0xffffffffu, s, o);
        if (lane == 0) {
            float sig = 1.f / (1.f + expf(-(s + bv)));
            float w = mask[rowbase + lrow] ? sig : 0.f;
            wrow[lrow] = w;
            rsout[rowbase + lrow] = w;
        }
    }
    __syncthreads();
    float acc = 0.f;
    #pragma unroll 4
    for (int i = 0; i < 128; i++) {
        float w = wrow[i];
        if (w != 0.f) acc += w * node[(size_t)(rowbase + i) * DD + tid];
    }
    sout[tid] = acc;
}

// ---------------- shared GEMM mainloop (cp.async dbuf + ldmatrix, ILP-ordered) ----------------
#define KCP2 40
#define GST_B 40960
#define GEMM_SMEM (2*GST_B)

__device__ __forceinline__ void gemm_mainloop(
        const __nv_bfloat16* __restrict__ Ahi, const __nv_bfloat16* __restrict__ Alo,
        const __nv_bfloat16* __restrict__ Wth, const __nv_bfloat16* __restrict__ Wtl,
        int bm, int bn, float c[2][8][4], char* smem) {
    uint32_t sb = (uint32_t)__cvta_generic_to_shared(smem);

    int tid = threadIdx.x, wid = tid >> 5, lane = tid & 31;
    int wm = wid >> 1, wn = wid & 1;
    int m8 = lane >> 3, r8 = lane & 7;
    int rowoff = r8 + ((m8 & 1) ? 8 : 0);
    int koff8 = (m8 >= 2) ? 8 : 0;

    auto issue = [&](int ch, int st) {
        uint32_t base = sb + st * GST_B;
        int k0 = ch * 32;
        #pragma unroll
        for (int it = 0; it < 2; it++) {
            int u = tid + it * 256;
            int row = u >> 2, c8 = u & 3;
            size_t src = (size_t)(bm + row) * DD + k0 + c8 * 8;
            CPA(base + row * 80 + c8 * 16, Ahi + src);
            CPA(base + 10240 + row * 80 + c8 * 16, Alo + src);
        }
        #pragma unroll
        for (int it = 0; it < 2; it++) {
            int u = tid + it * 256;
            int n = u >> 2, c8 = u & 3;
            size_t src = (size_t)(bn + n) * 256 + k0 + c8 * 8;
            CPA(base + 20480 + n * 80 + c8 * 16, Wth + src);
            CPA(base + 30720 + n * 80 + c8 * 16, Wtl + src);
        }
    };

    issue(0, 0);
    CPC();
    int buf = 0;
    for (int ch = 0; ch < 8; ch++) {
        bool hn = (ch < 7);
        if (hn) { issue(ch + 1, buf ^ 1); CPC(); }
        if (hn) { CPW1(); } else { CPW0(); }
        __syncthreads();
        uint32_t base = sb + buf * GST_B;
        #pragma unroll
        for (int kt = 0; kt < 2; kt++) {
            int kcol = kt * 16 + koff8;
            uint32_t ah[2][4], al[2][4];
            #pragma unroll
            for (int mt = 0; mt < 2; mt++) {
                uint32_t aoff = (uint32_t)((wm*32 + mt*16 + rowoff) * KCP2 + kcol) * 2;
                LDSM4(ah[mt][0], ah[mt][1], ah[mt][2], ah[mt][3], base + aoff);
                LDSM4(al[mt][0], al[mt][1], al[mt][2], al[mt][3], base + 10240 + aoff);
            }
            #pragma unroll
            for (int j = 0; j < 4; j++) {
                uint32_t woff = (uint32_t)((wn*64 + j*16 + rowoff) * KCP2 + kcol) * 2;
                uint32_t wh0, wh1, wh2, wh3, wl0, wl1, wl2, wl3;
                LDSM4(wh0, wh1, wh2, wh3, base + 20480 + woff);
                LDSM4(wl0, wl1, wl2, wl3, base + 30720 + woff);
                mma_bf16(c[0][2*j],   ah[0][0], ah[0][1], ah[0][2], ah[0][3], wh0, wh2);
                mma_bf16(c[1][2*j],   ah[1][0], ah[1][1], ah[1][2], ah[1][3], wh0, wh2);
                mma_bf16(c[0][2*j+1], ah[0][0], ah[0][1], ah[0][2], ah[0][3], wh1, wh3);
                mma_bf16(c[1][2*j+1], ah[1][0], ah[1][1], ah[1][2], ah[1][3], wh1, wh3);
                mma_bf16(c[0][2*j],   al[0][0], al[0][1], al[0][2], al[0][3], wh0, wh2);
                mma_bf16(c[1][2*j],   al[1][0], al[1][1], al[1][2], al[1][3], wh0, wh2);
                mma_bf16(c[0][2*j+1], al[0][0], al[0][1], al[0][2], al[0][3], wh1, wh3);
                mma_bf16(c[1][2*j+1], al[1][0], al[1][1], al[1][2], al[1][3], wh1, wh3);
                mma_bf16(c[0][2*j],   ah[0][0], ah[0][1], ah[0][2], ah[0][3], wl0, wl2);
                mma_bf16(c[1][2*j],   ah[1][0], ah[1][1], ah[1][2], ah[1][3], wl0, wl2);
                mma_bf16(c[0][2*j+1], ah[0][0], ah[0][1], ah[0][2], ah[0][3], wl1, wl3);
                mma_bf16(c[1][2*j+1], ah[1][0], ah[1][1], ah[1][2], ah[1][3], wl1, wl3);
            }
        }
        __syncthreads();
        buf ^= 1;
    }
}

__device__ __forceinline__ void gemm_epi_self(float c[2][8][4], float* Cself,
                                              const float* bias, int bm, int bn, int N) {
    int tid = threadIdx.x, wid = tid >> 5, lane = tid & 31;
    int wm = wid >> 1, wn = wid & 1;
    #pragma unroll
    for (int mt = 0; mt < 2; mt++)
        #pragma unroll
        for (int h = 0; h < 2; h++) {
            int row = bm + wm * 32 + mt * 16 + (lane >> 2) + h * 8;
            float* orow = Cself + (size_t)row * N;
            #pragma unroll
            for (int nt = 0; nt < 8; nt++) {
                int col = bn + wn * 64 + nt * 8 + (lane & 3) * 2;
                float2 o;
                o.x = c[mt][nt][h * 2 + 0] + bias[col];
                o.y = c[mt][nt][h * 2 + 1] + bias[col + 1];
                *(float2*)(orow + col) = o;
            }
        }
}

// step-phase GEMM + vec über-kernel
__global__ __launch_bounds__(256)
void gemm_all_kernel(const float* __restrict__ b_self,
                     const float* __restrict__ Wqd, const float* __restrict__ Wqup,
                     const float* __restrict__ Wquq) {
    extern __shared__ char gsm[];
    int idx = blockIdx.x;
    if (idx >= 386) {
        int v = idx - 386;
        int b = v & 3, sel = v >> 2, tid = threadIdx.x;
        float* sh = (float*)gsm;
        const float* W = (sel == 0) ? Wqd : (sel == 1) ? Wqup : Wquq;
        float* out = (sel == 0) ? g_vqd : (sel == 1) ? g_vqup : g_vquq;
        float sv = 0.f;
        if (sel < 2) {
            #pragma unroll
            for (int cc = 0; cc < 16; cc++) sv += g_sppart[(b*16 + cc)*DD + tid];
        } else {
            #pragma unroll
            for (int cc = 0; cc < 8; cc++) sv += g_sqpart[(b*8 + cc)*DD + tid];
        }
        sh[tid] = sv;
        __syncthreads();
        float acc = 0.f;
        #pragma unroll 8
        for (int k = 0; k < DD; k++) acc += sh[k] * W[(size_t)k*DD + tid];
        out[b*DD + tid] = acc;
        return;
    }
    const __nv_bfloat16 *Ahi, *Alo, *WthS, *WtlS, *WthY, *WtlY;
    float* Cself; const float* rowscale;
    __half* Yf; int NNbatch, bm, by;
    if (idx < 256) {
        by = idx >> 6; bm = (idx & 63) * 128;
        Ahi = g_Aphi; Alo = g_Aplo;
        WthY = g_Wth + OFF_PPW; WtlY = g_Wtl + OFF_PPW;
        Cself = g_selfp; rowscale = g_rsp; Yf = g_Ypf16; NNbatch = PP;
    } else if (idx < 384) {
        int i2 = idx - 256;
        by = i2 >> 5; bm = (i2 & 31) * 128;
        Ahi = g_Aqhi; Alo = g_Aqlo;
        WthY = g_Wth + OFF_QQW; WtlY = g_Wtl + OFF_QQW;
        Cself = g_selfq; rowscale = g_rsq; Yf = g_Yqf16; NNbatch = QQ;
    } else {
        by = idx - 384; bm = 0;
        Ahi = g_Aquhi; Alo = g_Aqulo;
        WthY = nullptr; WtlY = nullptr;
        Cself = g_selfqu; rowscale = nullptr; Yf = nullptr; NNbatch = 0;
    }
    WthS = g_Wth + OFF_SELF; WtlS = g_Wtl + OFF_SELF;
    int mode = by >> 1;
    int bn = (by & 1) * 128;
    const __nv_bfloat16* Wth = mode ? WthY : WthS;
    const __nv_bfloat16* Wtl = mode ? WtlY : WtlS;

    float c[2][8][4];
    #pragma unroll
    for (int mt = 0; mt < 2; mt++)
        #pragma unroll
        for (int nt = 0; nt < 8; nt++)
            #pragma unroll
            for (int r = 0; r < 4; r++) c[mt][nt][r] = 0.f;

    gemm_mainloop(Ahi, Alo, Wth, Wtl, bm, bn, c, gsm);

    int tid = threadIdx.x, wid = tid >> 5, lane = tid & 31;
    int wm = wid >> 1, wn = wid & 1;
    if (mode == 0) {
        gemm_epi_self(c, Cself, b_self, bm, bn, DD);
    } else {
        #pragma unroll
        for (int mt = 0; mt < 2; mt++)
            #pragma unroll
            for (int h = 0; h < 2; h++) {
                int gr = bm + wm * 32 + mt * 16 + (lane >> 2) + h * 8;
                float rs = rowscale[gr];
                int b = gr / NNbatch;
                int i = gr - b * NNbatch;
                #pragma unroll
                for (int nt = 0; nt < 8; nt++) {
                    int col = bn + wn * 64 + nt * 8 + (lane & 3) * 2;
                    size_t base = ((size_t)b * DD + col) * NNbatch + i;
                    Yf[base] = __float2half(c[mt][nt][h * 2 + 0] * rs);
                    Yf[base + NNbatch] = __float2half(c[mt][nt][h * 2 + 1] * rs);
                }
            }
    }
}

// merged output projections: [0,64) p, [64,96) q, 96 qu
__global__ __launch_bounds__(256)
void gemm_out_kernel(const float* __restrict__ b_p, const float* __restrict__ b_q,
                     const float* __restrict__ b_qu, float* __restrict__ out) {
    extern __shared__ char gsm[];
    int bx = blockIdx.x;
    const __nv_bfloat16 *Ahi, *Alo, *Wth, *Wtl; const float* bias; float* O; int bm;
    if (bx < 64) {
        Ahi = g_Aphi; Alo = g_Aplo; Wth = g_Wth + OFF_PW; Wtl = g_Wtl + OFF_PW;
        bias = b_p; O = out; bm = bx * 128;
    } else if (bx < 96) {
        Ahi = g_Aqhi; Alo = g_Aqlo; Wth = g_Wth + OFF_QW; Wtl = g_Wtl + OFF_QW;
        bias = b_q; O = out + (size_t)BB*PP*HH; bm = (bx - 64) * 128;
    } else {
        Ahi = g_Aquhi; Alo = g_Aqulo; Wth = g_Wth + OFF_QUW; Wtl = g_Wtl + OFF_QUW;
        bias = b_qu; O = out + (size_t)BB*PP*HH + (size_t)BB*QQ*HH; bm = 0;
    }
    float c[2][8][4];
    #pragma unroll
    for (int mt = 0; mt < 2; mt++)
        #pragma unroll
        for (int nt = 0; nt < 8; nt++)
            #pragma unroll
            for (int r = 0; r < 4; r++) c[mt][nt][r] = 0.f;

    gemm_mainloop(Ahi, Alo, Wth, Wtl, bm, 0, c, gsm);
    gemm_epi_self(c, O, bias, bm, 0, HH);
}

// ---------------- adjacency: fp16 single-product, 4-stage, 2 CTAs/SM + qu_update ----------------
#define KC 32
#define KCP 40
#define AS_B 5120
#define BH_B 10240
#define ST_B (AS_B + BH_B)         // 15360 per stage
#define ADJ_SMEM (4*ST_B)          // 61440

__global__ __launch_bounds__(256, 2)
void adjq_kernel(const float* __restrict__ selfp, const float* __restrict__ selfq,
                 float* __restrict__ Op, float* __restrict__ Oq,
                 float* __restrict__ qunxt) {
    extern __shared__ __align__(16) char dsm[];
    int bx = blockIdx.x;
    int tid = threadIdx.x;
    if (bx >= 384) {
        int r = bx - 384;
        int b = r / QNN;
        float v = g_selfqu[(size_t)r*DD + tid] + g_coefqu[r] * (g_vqup[b*DD + tid] + g_vquq[b*DD + tid]);
        qunxt[(size_t)r*DD + tid] = fmaxf(v, 0.f);
        return;
    }
    uint32_t smemBase = (uint32_t)__cvta_generic_to_shared(dsm);

    const __half *Gf, *Yf; const float *S, *coef, *ev;
    float* O; int NN, b, mtile, nhalf;
    if (bx < 256) {
        nhalf = bx & 1;
        int rest = bx >> 1;
        b = rest >> 5; mtile = rest & 31; NN = PP;
        Gf = g_Gpf16 + (size_t)b*PP*PP;
        Yf = g_Ypf16 + (size_t)b*DD*PP;
        S = selfp + (size_t)b*PP*DD;    coef = g_coefp + b*PP;
        ev = nullptr;                   O = Op + (size_t)b*PP*DD;
    } else {
        int i2 = bx - 256;
        nhalf = i2 & 1;
        int rest = i2 >> 1;
        b = rest >> 4; mtile = rest & 15; NN = QQ;
        Gf = g_Gqf16 + (size_t)b*QQ*QQ;
        Yf = g_Yqf16 + (size_t)b*DD*QQ;
        S = selfq + (size_t)b*QQ*DD;    coef = g_coefq + b*QQ;
        ev = g_vqd + b*DD;              O = Oq + (size_t)b*QQ*DD;
    }
    int bm = mtile * 64, bn = nhalf * 128;
    int wid = tid >> 5, lane = tid & 31;
    int wm = wid >> 2, wn = wid & 3;
    int m8 = lane >> 3, r8 = lane & 7;
    int rowoff = r8 + ((m8 & 1) ? 8 : 0);
    int koff8 = (m8 >= 2) ? 8 : 0;

    float c[2][4][4];
    #pragma unroll
    for (int mt = 0; mt < 2; mt++)
        #pragma unroll
        for (int nt = 0; nt < 4; nt++)
            #pragma unroll
            for (int r = 0; r < 4; r++) c[mt][nt][r] = 0.f;

    int arow = tid >> 2, ac8 = tid & 3;

    auto issue = [&](int k0, int stage) {
        uint32_t asb = smemBase + stage * ST_B;
        CPA(asb + arow * 80 + ac8 * 16, Gf + (size_t)(bm + arow) * NN + k0 + ac8 * 8);
        uint32_t bfb = asb + AS_B;
        #pragma unroll
        for (int it = 0; it < 2; it++) {
            int idx = tid + it * 256;
            int d = idx >> 2, c8 = idx & 3;
            size_t src = (size_t)(bn + d) * NN + k0 + c8 * 8;
            CPA(bfb + d * 80 + c8 * 16, Yf + src);
        }
    };

    const int nchunks = NN / KC;
    #pragma unroll
    for (int s = 0; s < 3; s++) { issue(s * KC, s); CPC(); }

    for (int ch = 0; ch < nchunks; ch++) {
        int rem = nchunks - 1 - ch;
        if (rem >= 2) { CPW2(); } else if (rem == 1) { CPW1(); } else { CPW0(); }
        __syncthreads();
        int nx = ch + 3;
        if (nx < nchunks) { issue(nx * KC, nx & 3); CPC(); }

        uint32_t stB = smemBase + (ch & 3) * ST_B;
        uint32_t asB = stB;
        uint32_t bfB = stB + AS_B;

        #pragma unroll
        for (int kt = 0; kt < 2; kt++) {
            int kcol = kt * 16 + koff8;
            uint32_t a[2][4];
            #pragma unroll
            for (int mt = 0; mt < 2; mt++) {
                uint32_t aoff = (uint32_t)((wm*32 + mt*16 + rowoff) * KCP + kcol) * 2;
                LDSM4(a[mt][0], a[mt][1], a[mt][2], a[mt][3], asB + aoff);
            }
            uint32_t bf[2][4];
            #pragma unroll
            for (int j = 0; j < 2; j++) {
                uint32_t boff = (uint32_t)((wn*32 + j*16 + rowoff) * KCP + kcol) * 2;
                LDSM4(bf[j][0], bf[j][1], bf[j][2], bf[j][3], bfB + boff);
            }
            // single fp16 pass: 8 independent accumulators
            mma_f16(c[0][0], a[0][0], a[0][1], a[0][2], a[0][3], bf[0][0], bf[0][2]);
            mma_f16(c[1][0], a[1][0], a[1][1], a[1][2], a[1][3], bf[0][0], bf[0][2]);
            mma_f16(c[0][1], a[0][0], a[0][1], a[0][2], a[0][3], bf[0][1], bf[0][3]);
            mma_f16(c[1][1], a[1][0], a[1][1], a[1][2], a[1][3], bf[0][1], bf[0][3]);
            mma_f16(c[0][2], a[0][0], a[0][1], a[0][2], a[0][3], bf[1][0], bf[1][2]);
            mma_f16(c[1][2], a[1][0], a[1][1], a[1][2], a[1][3], bf[1][0], bf[1][2]);
            mma_f16(c[0][3], a[0][0], a[0][1], a[0][2], a[0][3], bf[1][1], bf[1][3]);
            mma_f16(c[1][3], a[1][0], a[1][1], a[1][2], a[1][3], bf[1][1], bf[1][3]);
        }
    }

    #pragma unroll
    for (int mt = 0; mt < 2; mt++) {
        #pragma unroll
        for (int h = 0; h < 2; h++) {
            int row = bm + wm * 32 + mt * 16 + (lane >> 2) + h * 8;
            float cf = coef[row];
            const float* srow = S + (size_t)row * DD;
            float* orow = O + (size_t)row * DD;
            #pragma unroll
            for (int nt = 0; nt < 4; nt++) {
                int col = bn + wn * 32 + (nt >> 1) * 16 + (nt & 1) * 8 + (lane & 3) * 2;
                float v0 = c[mt][nt][h * 2 + 0];
                float v1 = c[mt][nt][h * 2 + 1];
                if (ev) { v0 += ev[col]; v1 += ev[col + 1]; }
                float2 s2 = *(const float2*)(srow + col);
                float2 o;
                o.x = fmaxf(s2.x + cf * v0, 0.f);
                o.y = fmaxf(s2.y + cf * v1, 0.f);
                *(float2*)(orow + col) = o;
            }
        }
    }
}

// ---------------- launch ----------------
extern "C" void kernel_launch(void* const* d_in, const int* in_sizes, int n_in,
                              void* d_out, int out_size) {
    const float* p_in   = (const float*)d_in[0];
    const float* q_in   = (const float*)d_in[1];
    const float* qu_in  = (const float*)d_in[2];
    const int*   pmask  = (const int*)d_in[3];
    const int*   qmask  = (const int*)d_in[4];
    const int*   qumask = (const int*)d_in[5];
    const int*   ppg    = (const int*)d_in[6];
    const int*   qqg    = (const int*)d_in[7];
    const float* W_node = (const float*)d_in[10];
    const float* b_node = (const float*)d_in[11];
    const float* W_self = (const float*)d_in[12];
    const float* b_self = (const float*)d_in[13];
    const float* W_pp   = (const float*)d_in[14];
    const float* W_qd   = (const float*)d_in[15];
    const float* W_qq   = (const float*)d_in[16];
    const float* W_qup  = (const float*)d_in[17];
    const float* W_quq  = (const float*)d_in[18];
    const float* W_p    = (const float*)d_in[19];
    const float* b_p    = (const float*)d_in[20];
    const float* W_q    = (const float*)d_in[21];
    const float* b_q    = (const float*)d_in[22];
    const float* W_qu   = (const float*)d_in[23];
    const float* b_qu   = (const float*)d_in[24];
    float* out = (float*)d_out;

    float *pA, *pB, *qA, *qB, *quA, *quB, *selfp, *selfq;
    cudaGetSymbolAddress((void**)&pA, g_pA);
    cudaGetSymbolAddress((void**)&pB, g_pB);
    cudaGetSymbolAddress((void**)&qA, g_qA);
    cudaGetSymbolAddress((void**)&qB, g_qB);
    cudaGetSymbolAddress((void**)&quA, g_quA);
    cudaGetSymbolAddress((void**)&quB, g_quB);
    cudaGetSymbolAddress((void**)&selfp, g_selfp);
    cudaGetSymbolAddress((void**)&selfq, g_selfq);

    cudaFuncSetAttribute(adjq_kernel, cudaFuncAttributeMaxDynamicSharedMemorySize, ADJ_SMEM);
    cudaFuncSetAttribute(gemm_all_kernel, cudaFuncAttributeMaxDynamicSharedMemorySize, GEMM_SMEM);
    cudaFuncSetAttribute(gemm_out_kernel, cudaFuncAttributeMaxDynamicSharedMemorySize, GEMM_SMEM);

    prep_kernel<<<1921, 256>>>(ppg, qqg, pmask, qmask, qumask,
                               W_self, W_pp, W_qq, W_p, W_q, W_qu);

    const float* pc = p_in;  const float* qc = q_in;  const float* quc = qu_in;
    float* pn = pA;  float* qn = qA;  float* qun = quA;

    for (int step = 0; step < 2; step++) {
        steppre_kernel<<<3200, 256>>>(pc, qc, quc, pmask, qmask, W_node, b_node);
        gemm_all_kernel<<<398, 256, GEMM_SMEM>>>(b_self, W_qd, W_qup, W_quq);
        adjq_kernel<<<512, 256, ADJ_SMEM>>>(selfp, selfq, pn, qn, qun);
        pc = pn; qc = qn; quc = qun;
        pn = pB; qn = qB; qun = quB;
    }

    asplit_all_kernel<<<3104, 256>>>(pc, qc, quc);
    gemm_out_kernel<<<97, 256, GEMM_SMEM>>>(b_p, b_q, b_qu, out);
}

// round 16
// speedup vs baseline: 1.6293x; 1.1763x over previous
#include <cuda_runtime.h>
#include <cuda_bf16.h>
#include <cuda_fp16.h>
#include <math.h>
#include <stdint.h>

#define BB  4
#define PP  2048
#define QQ  1024
#define QNN 32
#define DD  256
#define HH  128

// ---------------- persistent scratch ----------------
__device__ float g_pA[BB*PP*DD];
__device__ float g_pB[BB*PP*DD];
__device__ float g_qA[BB*QQ*DD];
__device__ float g_qB[BB*QQ*DD];
__device__ float g_quA[BB*QNN*DD];
__device__ float g_quB[BB*QNN*DD];
__device__ float g_selfp[BB*PP*DD];
__device__ float g_selfq[BB*QQ*DD];
__device__ float g_selfqu[BB*QNN*DD];
__device__ __half g_Ypf16[BB*DD*PP];
__device__ __half g_Yqf16[BB*DD*QQ];
__device__ __half g_Gpf16[(size_t)BB*PP*PP];
__device__ __half g_Gqf16[(size_t)BB*QQ*QQ];
__device__ __half g_Apf16[BB*PP*DD];
__device__ __half g_Aqf16[BB*QQ*DD];
__device__ __half g_Aquf16[BB*QNN*DD];
__device__ __half g_Wtf16[294912];
#define OFF_SELF 0
#define OFF_PPW  65536
#define OFF_QQW  131072
#define OFF_PW   196608
#define OFF_QW   229376
#define OFF_QUW  262144
__device__ float g_rsp[BB*PP];
__device__ float g_rsq[BB*QQ];
__device__ float g_coefp[BB*PP];
__device__ float g_coefq[BB*QQ];
__device__ float g_coefqu[BB*QNN];
__device__ float g_sppart[BB*16*DD];
__device__ float g_sqpart[BB*8*DD];
__device__ float g_vqd[BB*DD];
__device__ float g_vqup[BB*DD];
__device__ float g_vquq[BB*DD];

// ---------------- asm helpers ----------------
#define CPA(dst, src) asm volatile("cp.async.cg.shared.global [%0], [%1], 16;" :: "r"(dst), "l"(src) : "memory")
#define CPC() asm volatile("cp.async.commit_group;" ::: "memory")
#define CPW2() asm volatile("cp.async.wait_group 2;" ::: "memory")
#define CPW1() asm volatile("cp.async.wait_group 1;" ::: "memory")
#define CPW0() asm volatile("cp.async.wait_group 0;" ::: "memory")
#define LDSM4(r0, r1, r2, r3, addr) \
    asm volatile("ldmatrix.sync.aligned.m8n8.x4.shared.b16 {%0,%1,%2,%3}, [%4];" \
        : "=r"(r0), "=r"(r1), "=r"(r2), "=r"(r3) : "r"(addr))

__device__ __forceinline__ void mma_f16(float c[4], uint32_t a0, uint32_t a1,
                                        uint32_t a2, uint32_t a3,
                                        uint32_t b0, uint32_t b1) {
    asm volatile(
        "mma.sync.aligned.m16n8k16.row.col.f32.f16.f16.f32 "
        "{%0,%1,%2,%3}, {%4,%5,%6,%7}, {%8,%9}, {%0,%1,%2,%3};"
        : "+f"(c[0]), "+f"(c[1]), "+f"(c[2]), "+f"(c[3])
        : "r"(a0), "r"(a1), "r"(a2), "r"(a3), "r"(b0), "r"(b1));
}

__device__ __forceinline__ uint32_t pack_h2(float x, float y) {
    __half2 h = __floats2half2_rn(x, y);
    return *(uint32_t*)&h;
}

// ---------------- PREP über-kernel ----------------
__global__ __launch_bounds__(256)
void prep_kernel(const int* __restrict__ Gp, const int* __restrict__ Gq,
                 const int* __restrict__ pm, const int* __restrict__ qm,
                 const int* __restrict__ qum,
                 const float* __restrict__ W_self, const float* __restrict__ W_pp,
                 const float* __restrict__ W_qq, const float* __restrict__ W_p,
                 const float* __restrict__ W_q, const float* __restrict__ W_qu) {
    __shared__ float shp[2112];
    int bx = blockIdx.x, tid = threadIdx.x;
    if (bx < 1024) {
        int b = bx >> 8, xtile = bx & 255;
        for (int i = tid; i < PP; i += 256) shp[i] = (float)pm[b*PP + i];
        __syncthreads();
        int warp = tid >> 5, lane = tid & 31;
        int row = xtile * 8 + warp;
        const int* g = Gp + ((size_t)b*PP + row) * PP;
        __half* go = g_Gpf16 + ((size_t)b*PP + row) * PP;
        float s = 0.f;
        for (int j = lane * 4; j < PP; j += 128) {
            int4 v = *(const int4*)(g + j);
            uint32_t r0 = (v.x ? 0x3C00u : 0u) | ((v.y ? 0x3C00u : 0u) << 16);
            uint32_t r1 = (v.z ? 0x3C00u : 0u) | ((v.w ? 0x3C00u : 0u) << 16);
            *(uint2*)(go + j) = make_uint2(r0, r1);
            s += shp[j] * (float)v.x + shp[j+1] * (float)v.y
               + shp[j+2] * (float)v.z + shp[j+3] * (float)v.w;
        }
        #pragma unroll
        for (int o = 16; o; o >>= 1) s += __shfl_xor_sync(0xffffffffu, s, o);
        if (lane == 0)
            g_coefp[b*PP + row] = pm[b*PP + row] ? 1.f / fmaxf(s, 1.f) : 0.f;
    } else if (bx < 1536) {
        int i2 = bx - 1024;
        int b = i2 >> 7, xtile = i2 & 127;
        float ps = 0.f;
        for (int i = tid; i < PP; i += 256) ps += (float)pm[b*PP + i];
        for (int i = tid; i < QQ; i += 256) shp[i] = (float)qm[b*QQ + i];
        shp[1024 + tid] = ps;
        __syncthreads();
        if (tid < 128) shp[1024 + tid] += shp[1024 + tid + 128];
        __syncthreads();
        if (tid < 64) shp[1024 + tid] += shp[1024 + tid + 64];
        __syncthreads();
        if (tid < 32) {
            float v = shp[1024 + tid] + shp[1024 + tid + 32];
            #pragma unroll
            for (int o = 16; o; o >>= 1) v += __shfl_xor_sync(0xffffffffu, v, o);
            if (tid == 0) shp[2048] = v;
        }
        __syncthreads();
        float psum = shp[2048];
        int warp = tid >> 5, lane = tid & 31;
        int row = xtile * 8 + warp;
        const int* g = Gq + ((size_t)b*QQ + row) * QQ;
        __half* go = g_Gqf16 + ((size_t)b*QQ + row) * QQ;
        float s = 0.f;
        for (int j = lane * 4; j < QQ; j += 128) {
            int4 v = *(const int4*)(g + j);
            uint32_t r0 = (v.x ? 0x3C00u : 0u) | ((v.y ? 0x3C00u : 0u) << 16);
            uint32_t r1 = (v.z ? 0x3C00u : 0u) | ((v.w ? 0x3C00u : 0u) << 16);
            *(uint2*)(go + j) = make_uint2(r0, r1);
            s += shp[j] * (float)v.x + shp[j+1] * (float)v.y
               + shp[j+2] * (float)v.z + shp[j+3] * (float)v.w;
        }
        #pragma unroll
        for (int o = 16; o; o >>= 1) s += __shfl_xor_sync(0xffffffffu, s, o);
        if (lane == 0)
            g_coefq[b*QQ + row] = qm[b*QQ + row] ? 1.f / fmaxf(psum + s, 1.f) : 0.f;
    } else if (bx == 1536) {
        for (int b = 0; b < BB; b++) {
            float s = 0.f;
            for (int i = tid; i < PP; i += 256) s += (float)pm[b*PP + i];
            for (int i = tid; i < QQ; i += 256) s += (float)qm[b*QQ + i];
            shp[tid] = s;
            __syncthreads();
            for (int o = 128; o; o >>= 1) { if (tid < o) shp[tid] += shp[tid + o]; __syncthreads(); }
            if (tid == 0) shp[1024 + b] = shp[0];
            __syncthreads();
        }
        if (tid < BB*QNN) {
            int b = tid / QNN;
            g_coefqu[tid] = qum[tid] ? 1.f / fmaxf(shp[1024 + b], 1.f) : 0.f;
        }
    } else {
        int w = bx - 1537;
        int z = w / 64, ww = w % 64;
        const float* W; int N; int off;
        switch (z) {
            case 0: W = W_self; N = 256; off = OFF_SELF; break;
            case 1: W = W_pp;   N = 256; off = OFF_PPW;  break;
            case 2: W = W_qq;   N = 256; off = OFF_QQW;  break;
            case 3: W = W_p;    N = 128; off = OFF_PW;   break;
            case 4: W = W_q;    N = 128; off = OFF_QW;   break;
            default: W = W_qu;  N = 128; off = OFF_QUW;  break;
        }
        int nb = (ww & 7) * 32, kb = (ww >> 3) * 32;
        if (nb >= N) return;
        int tx = tid & 31, ty = tid >> 5;
        #pragma unroll
        for (int r = 0; r < 32; r += 8)
            shp[(ty + r) * 33 + tx] = W[(size_t)(kb + ty + r) * N + nb + tx];
        __syncthreads();
        __half* Wt = g_Wtf16 + off;
        #pragma unroll
        for (int r = 0; r < 32; r += 8) {
            int n = nb + ty + r, k = kb + tx;
            Wt[(size_t)n * 256 + k] = __float2half(shp[tx * 33 + ty + r]);
        }
    }
}

// ---------------- A -> fp16 convert ----------------
__device__ __forceinline__ void asplit_body(int lb, const float* __restrict__ P,
                                            const float* __restrict__ Q,
                                            const float* __restrict__ QU) {
    const float* A; __half* Af; int l2;
    if (lb < 2048) { A = P; Af = g_Apf16; l2 = lb; }
    else if (lb < 3072) { A = Q; Af = g_Aqf16; l2 = lb - 2048; }
    else { A = QU; Af = g_Aquf16; l2 = lb - 3072; }
    size_t i4 = ((size_t)l2 * 256 + threadIdx.x) * 4;
    float4 v = *(const float4*)(A + i4);
    *(uint2*)(Af + i4) = make_uint2(pack_h2(v.x, v.y), pack_h2(v.z, v.w));
}

__global__ void asplit_all_kernel(const float* __restrict__ P, const float* __restrict__ Q,
                                  const float* __restrict__ QU) {
    asplit_body(blockIdx.x, P, Q, QU);
}

// ---------------- step-pre über-kernel: pws + asplit ----------------
__global__ __launch_bounds__(256)
void steppre_kernel(const float* __restrict__ pcur, const float* __restrict__ qcur,
                    const float* __restrict__ qucur,
                    const int* __restrict__ pmask, const int* __restrict__ qmask,
                    const float* __restrict__ Wn, const float* __restrict__ bn) {
    int bx = blockIdx.x;
    if (bx >= 96) { asplit_body(bx - 96, pcur, qcur, qucur); return; }
    int b = bx / 24, chunk = bx % 24;
    int tid = threadIdx.x, wid = tid >> 5, lane = tid & 31;
    const float* node; const int* mask; float* rsout; float* sout; int rowbase;
    if (chunk < 16) {
        node = pcur + (size_t)b*PP*DD; mask = pmask + b*PP;
        rsout = g_rsp + b*PP; sout = g_sppart + (b*16 + chunk)*DD; rowbase = chunk * 128;
    } else {
        node = qcur + (size_t)b*QQ*DD; mask = qmask + b*QQ;
        rsout = g_rsq + b*QQ; sout = g_sqpart + (b*8 + (chunk - 16))*DD; rowbase = (chunk - 16) * 128;
    }
    __shared__ float wsh[DD];
    __shared__ float wrow[128];
    for (int k = tid; k < DD; k += 256) wsh[k] = Wn[k];
    __syncthreads();
    float bv = bn[0];
    #pragma unroll
    for (int r = 0; r < 16; r++) {
        int lrow = wid * 16 + r;
        const float* nrow = node + (size_t)(rowbase + lrow) * DD;
        float s = 0.f;
        #pragma unroll
        for (int k = lane; k < DD; k += 32) s += nrow[k] * wsh[k];
        #pragma unroll
        for (int o = 16; o; o >>= 1) s += __shfl_xor_sync(0xffffffffu, s, o);
        if (lane == 0) {
            float sig = 1.f / (1.f + expf(-(s + bv)));
            float w = mask[rowbase + lrow] ? sig : 0.f;
            wrow[lrow] = w;
            rsout[rowbase + lrow] = w;
        }
    }
    __syncthreads();
    float acc = 0.f;
    #pragma unroll 4
    for (int i = 0; i < 128; i++) {
        float w = wrow[i];
        if (w != 0.f) acc += w * node[(size_t)(rowbase + i) * DD + tid];
    }
    sout[tid] = acc;
}

// ---------------- fp16 single-product GEMM mainloop ----------------
#define KCP2 40
#define GST_B 20480   // A 10240 | W 10240
#define GEMM_SMEM (2*GST_B)

__device__ __forceinline__ void gemm_mainloop(
        const __half* __restrict__ Af, const __half* __restrict__ Wtf,
        int bm, int bn, float c[2][8][4], char* smem) {
    uint32_t sb = (uint32_t)__cvta_generic_to_shared(smem);

    int tid = threadIdx.x, wid = tid >> 5, lane = tid & 31;
    int wm = wid >> 1, wn = wid & 1;
    int m8 = lane >> 3, r8 = lane & 7;
    int rowoff = r8 + ((m8 & 1) ? 8 : 0);
    int koff8 = (m8 >= 2) ? 8 : 0;

    auto issue = [&](int ch, int st) {
        uint32_t base = sb + st * GST_B;
        int k0 = ch * 32;
        #pragma unroll
        for (int it = 0; it < 2; it++) {
            int u = tid + it * 256;
            int row = u >> 2, c8 = u & 3;
            size_t src = (size_t)(bm + row) * DD + k0 + c8 * 8;
            CPA(base + row * 80 + c8 * 16, Af + src);
        }
        #pragma unroll
        for (int it = 0; it < 2; it++) {
            int u = tid + it * 256;
            int n = u >> 2, c8 = u & 3;
            size_t src = (size_t)(bn + n) * 256 + k0 + c8 * 8;
            CPA(base + 10240 + n * 80 + c8 * 16, Wtf + src);
        }
    };

    issue(0, 0);
    CPC();
    int buf = 0;
    for (int ch = 0; ch < 8; ch++) {
        bool hn = (ch < 7);
        if (hn) { issue(ch + 1, buf ^ 1); CPC(); }
        if (hn) { CPW1(); } else { CPW0(); }
        __syncthreads();
        uint32_t base = sb + buf * GST_B;
        #pragma unroll
        for (int kt = 0; kt < 2; kt++) {
            int kcol = kt * 16 + koff8;
            uint32_t a[2][4];
            #pragma unroll
            for (int mt = 0; mt < 2; mt++) {
                uint32_t aoff = (uint32_t)((wm*32 + mt*16 + rowoff) * KCP2 + kcol) * 2;
                LDSM4(a[mt][0], a[mt][1], a[mt][2], a[mt][3], base + aoff);
            }
            #pragma unroll
            for (int j = 0; j < 4; j++) {
                uint32_t woff = (uint32_t)((wn*64 + j*16 + rowoff) * KCP2 + kcol) * 2;
                uint32_t w0, w1, w2, w3;
                LDSM4(w0, w1, w2, w3, base + 10240 + woff);
                mma_f16(c[0][2*j],   a[0][0], a[0][1], a[0][2], a[0][3], w0, w2);
                mma_f16(c[1][2*j],   a[1][0], a[1][1], a[1][2], a[1][3], w0, w2);
                mma_f16(c[0][2*j+1], a[0][0], a[0][1], a[0][2], a[0][3], w1, w3);
                mma_f16(c[1][2*j+1], a[1][0], a[1][1], a[1][2], a[1][3], w1, w3);
            }
        }
        __syncthreads();
        buf ^= 1;
    }
}

__device__ __forceinline__ void gemm_epi_self(float c[2][8][4], float* Cself,
                                              const float* bias, int bm, int bn, int N) {
    int tid = threadIdx.x, wid = tid >> 5, lane = tid & 31;
    int wm = wid >> 1, wn = wid & 1;
    #pragma unroll
    for (int mt = 0; mt < 2; mt++)
        #pragma unroll
        for (int h = 0; h < 2; h++) {
            int row = bm + wm * 32 + mt * 16 + (lane >> 2) + h * 8;
            float* orow = Cself + (size_t)row * N;
            #pragma unroll
            for (int nt = 0; nt < 8; nt++) {
                int col = bn + wn * 64 + nt * 8 + (lane & 3) * 2;
                float2 o;
                o.x = c[mt][nt][h * 2 + 0] + bias[col];
                o.y = c[mt][nt][h * 2 + 1] + bias[col + 1];
                *(float2*)(orow + col) = o;
            }
        }
}

// step-phase GEMM + vec über-kernel
__global__ __launch_bounds__(256)
void gemm_all_kernel(const float* __restrict__ b_self,
                     const float* __restrict__ Wqd, const float* __restrict__ Wqup,
                     const float* __restrict__ Wquq) {
    extern __shared__ char gsm[];
    int idx = blockIdx.x;
    if (idx >= 386) {
        int v = idx - 386;
        int b = v & 3, sel = v >> 2, tid = threadIdx.x;
        float* sh = (float*)gsm;
        const float* W = (sel == 0) ? Wqd : (sel == 1) ? Wqup : Wquq;
        float* out = (sel == 0) ? g_vqd : (sel == 1) ? g_vqup : g_vquq;
        float sv = 0.f;
        if (sel < 2) {
            #pragma unroll
            for (int cc = 0; cc < 16; cc++) sv += g_sppart[(b*16 + cc)*DD + tid];
        } else {
            #pragma unroll
            for (int cc = 0; cc < 8; cc++) sv += g_sqpart[(b*8 + cc)*DD + tid];
        }
        sh[tid] = sv;
        __syncthreads();
        float acc = 0.f;
        #pragma unroll 8
        for (int k = 0; k < DD; k++) acc += sh[k] * W[(size_t)k*DD + tid];
        out[b*DD + tid] = acc;
        return;
    }
    const __half *Af, *WtS, *WtY;
    float* Cself; const float* rowscale;
    __half* Yf; int NNbatch, bm, by;
    if (idx < 256) {
        by = idx >> 6; bm = (idx & 63) * 128;
        Af = g_Apf16;
        WtY = g_Wtf16 + OFF_PPW;
        Cself = g_selfp; rowscale = g_rsp; Yf = g_Ypf16; NNbatch = PP;
    } else if (idx < 384) {
        int i2 = idx - 256;
        by = i2 >> 5; bm = (i2 & 31) * 128;
        Af = g_Aqf16;
        WtY = g_Wtf16 + OFF_QQW;
        Cself = g_selfq; rowscale = g_rsq; Yf = g_Yqf16; NNbatch = QQ;
    } else {
        by = idx - 384; bm = 0;
        Af = g_Aquf16;
        WtY = nullptr;
        Cself = g_selfqu; rowscale = nullptr; Yf = nullptr; NNbatch = 0;
    }
    WtS = g_Wtf16 + OFF_SELF;
    int mode = by >> 1;
    int bn = (by & 1) * 128;
    const __half* Wt = mode ? WtY : WtS;

    float c[2][8][4];
    #pragma unroll
    for (int mt = 0; mt < 2; mt++)
        #pragma unroll
        for (int nt = 0; nt < 8; nt++)
            #pragma unroll
            for (int r = 0; r < 4; r++) c[mt][nt][r] = 0.f;

    gemm_mainloop(Af, Wt, bm, bn, c, gsm);

    int tid = threadIdx.x, wid = tid >> 5, lane = tid & 31;
    int wm = wid >> 1, wn = wid & 1;
    if (mode == 0) {
        gemm_epi_self(c, Cself, b_self, bm, bn, DD);
    } else {
        #pragma unroll
        for (int mt = 0; mt < 2; mt++)
            #pragma unroll
            for (int h = 0; h < 2; h++) {
                int gr = bm + wm * 32 + mt * 16 + (lane >> 2) + h * 8;
                float rs = rowscale[gr];
                int b = gr / NNbatch;
                int i = gr - b * NNbatch;
                #pragma unroll
                for (int nt = 0; nt < 8; nt++) {
                    int col = bn + wn * 64 + nt * 8 + (lane & 3) * 2;
                    size_t base = ((size_t)b * DD + col) * NNbatch + i;
                    Yf[base] = __float2half(c[mt][nt][h * 2 + 0] * rs);
                    Yf[base + NNbatch] = __float2half(c[mt][nt][h * 2 + 1] * rs);
                }
            }
    }
}

// merged output projections: [0,64) p, [64,96) q, 96 qu
__global__ __launch_bounds__(256)
void gemm_out_kernel(const float* __restrict__ b_p, const float* __restrict__ b_q,
                     const float* __restrict__ b_qu, float* __restrict__ out) {
    extern __shared__ char gsm[];
    int bx = blockIdx.x;
    const __half *Af, *Wt; const float* bias; float* O; int bm;
    if (bx < 64) {
        Af = g_Apf16; Wt = g_Wtf16 + OFF_PW;
        bias = b_p; O = out; bm = bx * 128;
    } else if (bx < 96) {
        Af = g_Aqf16; Wt = g_Wtf16 + OFF_QW;
        bias = b_q; O = out + (size_t)BB*PP*HH; bm = (bx - 64) * 128;
    } else {
        Af = g_Aquf16; Wt = g_Wtf16 + OFF_QUW;
        bias = b_qu; O = out + (size_t)BB*PP*HH + (size_t)BB*QQ*HH; bm = 0;
    }
    float c[2][8][4];
    #pragma unroll
    for (int mt = 0; mt < 2; mt++)
        #pragma unroll
        for (int nt = 0; nt < 8; nt++)
            #pragma unroll
            for (int r = 0; r < 4; r++) c[mt][nt][r] = 0.f;

    gemm_mainloop(Af, Wt, bm, 0, c, gsm);
    gemm_epi_self(c, O, bias, bm, 0, HH);
}

// ---------------- adjacency: fp16 single-product, 4-stage, 2 CTAs/SM + qu_update ----------------
#define KC 32
#define KCP 40
#define AS_B 5120
#define BH_B 10240
#define ST_B (AS_B + BH_B)         // 15360 per stage
#define ADJ_SMEM (4*ST_B)          // 61440

__global__ __launch_bounds__(256, 2)
void adjq_kernel(const float* __restrict__ selfp, const float* __restrict__ selfq,
                 float* __restrict__ Op, float* __restrict__ Oq,
                 float* __restrict__ qunxt) {
    extern __shared__ __align__(16) char dsm[];
    int bx = blockIdx.x;
    int tid = threadIdx.x;
    if (bx >= 384) {
        int r = bx - 384;
        int b = r / QNN;
        float v = g_selfqu[(size_t)r*DD + tid] + g_coefqu[r] * (g_vqup[b*DD + tid] + g_vquq[b*DD + tid]);
        qunxt[(size_t)r*DD + tid] = fmaxf(v, 0.f);
        return;
    }
    uint32_t smemBase = (uint32_t)__cvta_generic_to_shared(dsm);

    const __half *Gf, *Yf; const float *S, *coef, *ev;
    float* O; int NN, b, mtile, nhalf;
    if (bx < 256) {
        nhalf = bx & 1;
        int rest = bx >> 1;
        b = rest >> 5; mtile = rest & 31; NN = PP;
        Gf = g_Gpf16 + (size_t)b*PP*PP;
        Yf = g_Ypf16 + (size_t)b*DD*PP;
        S = selfp + (size_t)b*PP*DD;    coef = g_coefp + b*PP;
        ev = nullptr;                   O = Op + (size_t)b*PP*DD;
    } else {
        int i2 = bx - 256;
        nhalf = i2 & 1;
        int rest = i2 >> 1;
        b = rest >> 4; mtile = rest & 15; NN = QQ;
        Gf = g_Gqf16 + (size_t)b*QQ*QQ;
        Yf = g_Yqf16 + (size_t)b*DD*QQ;
        S = selfq + (size_t)b*QQ*DD;    coef = g_coefq + b*QQ;
        ev = g_vqd + b*DD;              O = Oq + (size_t)b*QQ*DD;
    }
    int bm = mtile * 64, bn = nhalf * 128;
    int wid = tid >> 5, lane = tid & 31;
    int wm = wid >> 2, wn = wid & 3;
    int m8 = lane >> 3, r8 = lane & 7;
    int rowoff = r8 + ((m8 & 1) ? 8 : 0);
    int koff8 = (m8 >= 2) ? 8 : 0;

    float c[2][4][4];
    #pragma unroll
    for (int mt = 0; mt < 2; mt++)
        #pragma unroll
        for (int nt = 0; nt < 4; nt++)
            #pragma unroll
            for (int r = 0; r < 4; r++) c[mt][nt][r] = 0.f;

    int arow = tid >> 2, ac8 = tid & 3;

    auto issue = [&](int k0, int stage) {
        uint32_t asb = smemBase + stage * ST_B;
        CPA(asb + arow * 80 + ac8 * 16, Gf + (size_t)(bm + arow) * NN + k0 + ac8 * 8);
        uint32_t bfb = asb + AS_B;
        #pragma unroll
        for (int it = 0; it < 2; it++) {
            int idx = tid + it * 256;
            int d = idx >> 2, c8 = idx & 3;
            size_t src = (size_t)(bn + d) * NN + k0 + c8 * 8;
            CPA(bfb + d * 80 + c8 * 16, Yf + src);
        }
    };

    const int nchunks = NN / KC;
    #pragma unroll
    for (int s = 0; s < 3; s++) { issue(s * KC, s); CPC(); }

    for (int ch = 0; ch < nchunks; ch++) {
        int rem = nchunks - 1 - ch;
        if (rem >= 2) { CPW2(); } else if (rem == 1) { CPW1(); } else { CPW0(); }
        __syncthreads();
        int nx = ch + 3;
        if (nx < nchunks) { issue(nx * KC, nx & 3); CPC(); }

        uint32_t stB = smemBase + (ch & 3) * ST_B;
        uint32_t asB = stB;
        uint32_t bfB = stB + AS_B;

        #pragma unroll
        for (int kt = 0; kt < 2; kt++) {
            int kcol = kt * 16 + koff8;
            uint32_t a[2][4];
            #pragma unroll
            for (int mt = 0; mt < 2; mt++) {
                uint32_t aoff = (uint32_t)((wm*32 + mt*16 + rowoff) * KCP + kcol) * 2;
                LDSM4(a[mt][0], a[mt][1], a[mt][2], a[mt][3], asB + aoff);
            }
            uint32_t bf[2][4];
            #pragma unroll
            for (int j = 0; j < 2; j++) {
                uint32_t boff = (uint32_t)((wn*32 + j*16 + rowoff) * KCP + kcol) * 2;
                LDSM4(bf[j][0], bf[j][1], bf[j][2], bf[j][3], bfB + boff);
            }
            mma_f16(c[0][0], a[0][0], a[0][1], a[0][2], a[0][3], bf[0][0], bf[0][2]);
            mma_f16(c[1][0], a[1][0], a[1][1], a[1][2], a[1][3], bf[0][0], bf[0][2]);
            mma_f16(c[0][1], a[0][0], a[0][1], a[0][2], a[0][3], bf[0][1], bf[0][3]);
            mma_f16(c[1][1], a[1][0], a[1][1], a[1][2], a[1][3], bf[0][1], bf[0][3]);
            mma_f16(c[0][2], a[0][0], a[0][1], a[0][2], a[0][3], bf[1][0], bf[1][2]);
            mma_f16(c[1][2], a[1][0], a[1][1], a[1][2], a[1][3], bf[1][0], bf[1][2]);
            mma_f16(c[0][3], a[0][0], a[0][1], a[0][2], a[0][3], bf[1][1], bf[1][3]);
            mma_f16(c[1][3], a[1][0], a[1][1], a[1][2], a[1][3], bf[1][1], bf[1][3]);
        }
    }

    #pragma unroll
    for (int mt = 0; mt < 2; mt++) {
        #pragma unroll
        for (int h = 0; h < 2; h++) {
            int row = bm + wm * 32 + mt * 16 + (lane >> 2) + h * 8;
            float cf = coef[row];
            const float* srow = S + (size_t)row * DD;
            float* orow = O + (size_t)row * DD;
            #pragma unroll
            for (int nt = 0; nt < 4; nt++) {
                int col = bn + wn * 32 + (nt >> 1) * 16 + (nt & 1) * 8 + (lane & 3) * 2;
                float v0 = c[mt][nt][h * 2 + 0];
                float v1 = c[mt][nt][h * 2 + 1];
                if (ev) { v0 += ev[col]; v1 += ev[col + 1]; }
                float2 s2 = *(const float2*)(srow + col);
                float2 o;
                o.x = fmaxf(s2.x + cf * v0, 0.f);
                o.y = fmaxf(s2.y + cf * v1, 0.f);
                *(float2*)(orow + col) = o;
            }
        }
    }
}

// ---------------- launch ----------------
extern "C" void kernel_launch(void* const* d_in, const int* in_sizes, int n_in,
                              void* d_out, int out_size) {
    const float* p_in   = (const float*)d_in[0];
    const float* q_in   = (const float*)d_in[1];
    const float* qu_in  = (const float*)d_in[2];
    const int*   pmask  = (const int*)d_in[3];
    const int*   qmask  = (const int*)d_in[4];
    const int*   qumask = (const int*)d_in[5];
    const int*   ppg    = (const int*)d_in[6];
    const int*   qqg    = (const int*)d_in[7];
    const float* W_node = (const float*)d_in[10];
    const float* b_node = (const float*)d_in[11];
    const float* W_self = (const float*)d_in[12];
    const float* b_self = (const float*)d_in[13];
    const float* W_pp   = (const float*)d_in[14];
    const float* W_qd   = (const float*)d_in[15];
    const float* W_qq   = (const float*)d_in[16];
    const float* W_qup  = (const float*)d_in[17];
    const float* W_quq  = (const float*)d_in[18];
    const float* W_p    = (const float*)d_in[19];
    const float* b_p    = (const float*)d_in[20];
    const float* W_q    = (const float*)d_in[21];
    const float* b_q    = (const float*)d_in[22];
    const float* W_qu   = (const float*)d_in[23];
    const float* b_qu   = (const float*)d_in[24];
    float* out = (float*)d_out;

    float *pA, *pB, *qA, *qB, *quA, *quB, *selfp, *selfq;
    cudaGetSymbolAddress((void**)&pA, g_pA);
    cudaGetSymbolAddress((void**)&pB, g_pB);
    cudaGetSymbolAddress((void**)&qA, g_qA);
    cudaGetSymbolAddress((void**)&qB, g_qB);
    cudaGetSymbolAddress((void**)&quA, g_quA);
    cudaGetSymbolAddress((void**)&quB, g_quB);
    cudaGetSymbolAddress((void**)&selfp, g_selfp);
    cudaGetSymbolAddress((void**)&selfq, g_selfq);

    cudaFuncSetAttribute(adjq_kernel, cudaFuncAttributeMaxDynamicSharedMemorySize, ADJ_SMEM);
    cudaFuncSetAttribute(gemm_all_kernel, cudaFuncAttributeMaxDynamicSharedMemorySize, GEMM_SMEM);
    cudaFuncSetAttribute(gemm_out_kernel, cudaFuncAttributeMaxDynamicSharedMemorySize, GEMM_SMEM);

    prep_kernel<<<1921, 256>>>(ppg, qqg, pmask, qmask, qumask,
                               W_self, W_pp, W_qq, W_p, W_q, W_qu);

    const float* pc = p_in;  const float* qc = q_in;  const float* quc = qu_in;
    float* pn = pA;  float* qn = qA;  float* qun = quA;

    for (int step = 0; step < 2; step++) {
        steppre_kernel<<<3200, 256>>>(pc, qc, quc, pmask, qmask, W_node, b_node);
        gemm_all_kernel<<<398, 256, GEMM_SMEM>>>(b_self, W_qd, W_qup, W_quq);
        adjq_kernel<<<512, 256, ADJ_SMEM>>>(selfp, selfq, pn, qn, qun);
        pc = pn; qc = qn; quc = qun;
        pn = pB; qn = qB; qun = quB;
    }

    asplit_all_kernel<<<3104, 256>>>(pc, qc, quc);
    gemm_out_kernel<<<97, 256, GEMM_SMEM>>>(b_p, b_q, b_qu, out);
}